// round 13
// baseline (speedup 1.0000x reference)
#include <cuda_runtime.h>
#include <cuda_fp16.h>
#include <cuda_bf16.h>
#include <cstdint>

#define N_NODES 100000
#define N_EDGES 1000000
#define N_GRAPHS 512
#define HDIM 64
#define BKT 64   // slots per node (max observed in-degree ~35 for Poisson(10))

// ---------------- scratch (device globals; never passed from host) --------
// g_cnt is self-cleaning: k_gather64_f zeroes it after its final read, so
// every call starts from zero (globals are zero-initialized at load).
__device__ __align__(16) float  g_dinv[N_NODES];
__device__ __align__(16) int    g_cnt [N_NODES];
__device__ __align__(16) int    g_bkt [N_NODES * BKT];    // src indices
__device__ __align__(16) float  g_xs  [N_NODES * 8];      // dinv[n]*x[n]
__device__ __align__(16) __half g_xwh [N_NODES * HDIM];   // y = dinv*xw (fp16)
__device__ __align__(16) __half g_aggh[N_NODES * HDIM];   // h = relu(preact+b) fp16
__device__ __align__(16) float  g_agg [N_NODES * HDIM];   // fp32 preact4 (for pool)
__device__ __align__(16) float  g_gmax[N_GRAPHS * HDIM];
__device__ __align__(16) float  g_gsum[N_GRAPHS * HDIM];
__device__ float g_gcnt[N_GRAPHS];

__device__ __forceinline__ uint32_t smem_u32(const void* p) {
    return (uint32_t)__cvta_generic_to_shared(p);
}

// ---------------- bucket fill: single pass, 4 edges/thread ----------------
__global__ void k_fill(const int* __restrict__ rows, const int* __restrict__ cols) {
    int q = blockIdx.x * blockDim.x + threadIdx.x;
    if (q >= N_EDGES / 4) return;
    int4 r4 = ((const int4*)rows)[q];
    int4 c4 = ((const int4*)cols)[q];
    int s0 = atomicAdd(&g_cnt[c4.x], 1);
    int s1 = atomicAdd(&g_cnt[c4.y], 1);
    int s2 = atomicAdd(&g_cnt[c4.z], 1);
    int s3 = atomicAdd(&g_cnt[c4.w], 1);
    if (s0 < BKT) g_bkt[c4.x * BKT + s0] = r4.x;
    if (s1 < BKT) g_bkt[c4.y * BKT + s1] = r4.y;
    if (s2 < BKT) g_bkt[c4.z * BKT + s2] = r4.z;
    if (s3 < BKT) g_bkt[c4.w * BKT + s3] = r4.w;
}

// ---------------- prep: dinv from counts + xs prescale + zero pools -------
__global__ void k_prep(const float* __restrict__ x) {
    int n = blockIdx.x * blockDim.x + threadIdx.x;
    if (n < N_NODES) {
        int c = min(g_cnt[n], BKT);
        float dv = rsqrtf((float)(c + 1));   // +1 self-loop
        g_dinv[n] = dv;
        float4 a = ((const float4*)x)[(long)n * 2];
        float4 b = ((const float4*)x)[(long)n * 2 + 1];
        a.x *= dv; a.y *= dv; a.z *= dv; a.w *= dv;
        b.x *= dv; b.y *= dv; b.z *= dv; b.w *= dv;
        ((float4*)g_xs)[(long)n * 2]     = a;
        ((float4*)g_xs)[(long)n * 2 + 1] = b;
    }
    if (n < N_GRAPHS * HDIM) { g_gmax[n] = 0.0f; g_gsum[n] = 0.0f; }
    if (n < N_GRAPHS) g_gcnt[n] = 0.0f;
}

// ---------------- layer 1 fused: g_aggh = relu((A_hat@x)@W1 + b1) fp16 ----
// Block 256 threads = 128 nodes; 2 thr/node (cnt uniform across the pair).
__global__ void k_l1(const float* __restrict__ W1, const float* __restrict__ b1) {
    __shared__ __align__(16) float W1s[8 * 64];
    __shared__ __align__(16) float A[128 * 8];
    const int tid  = threadIdx.x;
    const int nloc = tid >> 1;
    const int half = tid & 1;
    const int n    = blockIdx.x * 128 + nloc;

    for (int i = tid; i < 512; i += 256) W1s[i] = W1[i];

    if (n < N_NODES) {
        const float4* xs4 = (const float4*)g_xs;
        const int4* bkt4 = (const int4*)&g_bkt[(long)n * BKT];
        int cnt = min(g_cnt[n], BKT);
        float4 acc = xs4[(long)n * 2 + half];   // own scaled row
        for (int i = 0; i < cnt; i += 4) {
            int4 r = bkt4[i >> 2];
            if (i + 0 < cnt) {
                float4 v = xs4[(long)r.x * 2 + half];
                acc.x += v.x; acc.y += v.y; acc.z += v.z; acc.w += v.w;
            }
            if (i + 1 < cnt) {
                float4 v = xs4[(long)r.y * 2 + half];
                acc.x += v.x; acc.y += v.y; acc.z += v.z; acc.w += v.w;
            }
            if (i + 2 < cnt) {
                float4 v = xs4[(long)r.z * 2 + half];
                acc.x += v.x; acc.y += v.y; acc.z += v.z; acc.w += v.w;
            }
            if (i + 3 < cnt) {
                float4 v = xs4[(long)r.w * 2 + half];
                acc.x += v.x; acc.y += v.y; acc.z += v.z; acc.w += v.w;
            }
        }
        float dv = g_dinv[n];
        acc.x *= dv; acc.y *= dv; acc.z *= dv; acc.w *= dv;
        *(float4*)&A[nloc * 8 + half * 4] = acc;
    }
    __syncthreads();

    if (n < N_NODES) {
        float a[8];
        *(float4*)&a[0] = *(const float4*)&A[nloc * 8];
        *(float4*)&a[4] = *(const float4*)&A[nloc * 8 + 4];
        const int jc0 = half * 32;
        float4 acc[8];
#pragma unroll
        for (int g = 0; g < 8; g++) acc[g] = make_float4(0.f, 0.f, 0.f, 0.f);
#pragma unroll
        for (int k = 0; k < 8; k++) {
            float ak = a[k];
#pragma unroll
            for (int g = 0; g < 8; g++) {
                float4 w = *(const float4*)&W1s[k * 64 + jc0 + g * 4];
                acc[g].x = fmaf(ak, w.x, acc[g].x);
                acc[g].y = fmaf(ak, w.y, acc[g].y);
                acc[g].z = fmaf(ak, w.z, acc[g].z);
                acc[g].w = fmaf(ak, w.w, acc[g].w);
            }
        }
        // epilogue: h1 = relu(preact1 + b1) -> fp16
#pragma unroll
        for (int g = 0; g < 8; g++) {
            int j = jc0 + g * 4;
            float4 bb = *(const float4*)&b1[j];
            __half2 p0 = __floats2half2_rn(fmaxf(acc[g].x + bb.x, 0.f),
                                           fmaxf(acc[g].y + bb.y, 0.f));
            __half2 p1 = __floats2half2_rn(fmaxf(acc[g].z + bb.z, 0.f),
                                           fmaxf(acc[g].w + bb.w, 0.f));
            __half2 pair[2] = {p0, p1};
            *(uint2*)&g_aggh[(long)n * 64 + j] = *(uint2*)pair;
        }
    }
}

// ---------------- gather64_h: g_aggh = relu(dinv*(y[c]+sum y[r]) + b) fp16
// Warp per node; cnt is warp-uniform -> guards are non-divergent.
__global__ void k_gather64_h(const float* __restrict__ bias) {
    int n = (blockIdx.x * blockDim.x + threadIdx.x) >> 5;
    int lane = threadIdx.x & 31;
    if (n >= N_NODES) return;
    const __half2* __restrict__ xw2 = (const __half2*)g_xwh;
    const int4* bkt4 = (const int4*)&g_bkt[(long)n * BKT];
    int cnt = min(g_cnt[n], BKT);
    float2 acc = __half22float2(xw2[(long)n * 32 + lane]);  // own y row
    for (int i = 0; i < cnt; i += 4) {
        int4 r = bkt4[i >> 2];
        if (i + 0 < cnt) {
            float2 v = __half22float2(xw2[(long)r.x * 32 + lane]);
            acc.x += v.x; acc.y += v.y;
        }
        if (i + 1 < cnt) {
            float2 v = __half22float2(xw2[(long)r.y * 32 + lane]);
            acc.x += v.x; acc.y += v.y;
        }
        if (i + 2 < cnt) {
            float2 v = __half22float2(xw2[(long)r.z * 32 + lane]);
            acc.x += v.x; acc.y += v.y;
        }
        if (i + 3 < cnt) {
            float2 v = __half22float2(xw2[(long)r.w * 32 + lane]);
            acc.x += v.x; acc.y += v.y;
        }
    }
    float dv = g_dinv[n];
    float2 bb = *(const float2*)&bias[lane * 2];
    ((__half2*)g_aggh)[(long)n * 32 + lane] =
        __floats2half2_rn(fmaxf(acc.x * dv + bb.x, 0.f),
                          fmaxf(acc.y * dv + bb.y, 0.f));
}

// ---------------- gather64_f: g_agg = dinv*(y[c]+sum y[r]) fp32 (final) ---
// Also self-cleans g_cnt for the next call (after its final read).
__global__ void k_gather64_f() {
    int n = (blockIdx.x * blockDim.x + threadIdx.x) >> 5;
    int lane = threadIdx.x & 31;
    if (n >= N_NODES) return;
    const __half2* __restrict__ xw2 = (const __half2*)g_xwh;
    const int4* bkt4 = (const int4*)&g_bkt[(long)n * BKT];
    int cnt = min(g_cnt[n], BKT);
    if (lane == 0) g_cnt[n] = 0;   // clean for next call (last reader)
    float2 acc = __half22float2(xw2[(long)n * 32 + lane]);
    for (int i = 0; i < cnt; i += 4) {
        int4 r = bkt4[i >> 2];
        if (i + 0 < cnt) {
            float2 v = __half22float2(xw2[(long)r.x * 32 + lane]);
            acc.x += v.x; acc.y += v.y;
        }
        if (i + 1 < cnt) {
            float2 v = __half22float2(xw2[(long)r.y * 32 + lane]);
            acc.x += v.x; acc.y += v.y;
        }
        if (i + 2 < cnt) {
            float2 v = __half22float2(xw2[(long)r.z * 32 + lane]);
            acc.x += v.x; acc.y += v.y;
        }
        if (i + 3 < cnt) {
            float2 v = __half22float2(xw2[(long)r.w * 32 + lane]);
            acc.x += v.x; acc.y += v.y;
        }
    }
    float dv = g_dinv[n];
    acc.x *= dv; acc.y *= dv;
    ((float2*)g_agg)[(long)n * 32 + lane] = acc;
}

// ---------------- GEMM K=64 tensor cores: g_xwh = dinv * (g_aggh @ W) -----
__global__ __launch_bounds__(256) void k_gemmT(const float* __restrict__ W) {
    __shared__ __align__(16) __half Sh[64 * 72];  // A fp16
    __shared__ __align__(16) __half Wh[64 * 72];  // W fp16
    __shared__ float Dv[64];
    const int tid  = threadIdx.x;
    const int base = blockIdx.x * 64;

    if (tid < 64) {
        int row = base + tid;
        Dv[tid] = (row < N_NODES) ? g_dinv[row] : 0.0f;
    }
    // stage A: copy fp16 rows
    for (int i = tid; i < 1024; i += 256) {
        int r = i >> 4, k4 = i & 15;
        int row = base + r;
        uint2 v = make_uint2(0u, 0u);
        if (row < N_NODES) v = *(const uint2*)&g_aggh[(long)row * 64 + k4 * 4];
        *(uint2*)&Sh[r * 72 + k4 * 4] = v;
    }
    // stage W -> fp16
    for (int i = tid; i < 2048; i += 256) {
        int k = i >> 5, j2 = i & 31;
        float2 w = *(const float2*)&W[k * 64 + j2 * 2];
        ((__half2*)Wh)[k * 36 + j2] = __floats2half2_rn(w.x, w.y);
    }
    __syncthreads();

    const int warp = tid >> 5, lane = tid & 31;
    const int m_base = (warp >> 1) * 16;
    const int n_base = (warp & 1) * 32;
    const int lt   = lane & 7;
    const int tile = lane >> 3;

    float d[4][4];
#pragma unroll
    for (int nt = 0; nt < 4; nt++)
#pragma unroll
        for (int q = 0; q < 4; q++) d[nt][q] = 0.f;

#pragma unroll
    for (int kc = 0; kc < 4; kc++) {
        int arow = m_base + lt + ((tile & 1) ? 8 : 0);
        int acol = kc * 16 + ((tile & 2) ? 8 : 0);
        uint32_t a0, a1, a2, a3;
        {
            uint32_t addr = smem_u32(&Sh[arow * 72 + acol]);
            asm volatile("ldmatrix.sync.aligned.m8n8.x4.shared.b16 {%0,%1,%2,%3}, [%4];"
                         : "=r"(a0), "=r"(a1), "=r"(a2), "=r"(a3) : "r"(addr));
        }
#pragma unroll
        for (int g = 0; g < 2; g++) {
            int krow = kc * 16 + lt + ((tile & 1) ? 8 : 0);
            int bcol = n_base + g * 16 + ((tile & 2) ? 8 : 0);
            uint32_t b0, b1, b2, b3;
            uint32_t addr = smem_u32(&Wh[krow * 72 + bcol]);
            asm volatile("ldmatrix.sync.aligned.m8n8.x4.trans.shared.b16 {%0,%1,%2,%3}, [%4];"
                         : "=r"(b0), "=r"(b1), "=r"(b2), "=r"(b3) : "r"(addr));
            asm volatile("mma.sync.aligned.m16n8k16.row.col.f32.f16.f16.f32 "
                         "{%0,%1,%2,%3},{%4,%5,%6,%7},{%8,%9},{%0,%1,%2,%3};"
                         : "+f"(d[g*2][0]), "+f"(d[g*2][1]), "+f"(d[g*2][2]), "+f"(d[g*2][3])
                         : "r"(a0), "r"(a1), "r"(a2), "r"(a3), "r"(b0), "r"(b1));
            asm volatile("mma.sync.aligned.m16n8k16.row.col.f32.f16.f16.f32 "
                         "{%0,%1,%2,%3},{%4,%5,%6,%7},{%8,%9},{%0,%1,%2,%3};"
                         : "+f"(d[g*2+1][0]), "+f"(d[g*2+1][1]), "+f"(d[g*2+1][2]), "+f"(d[g*2+1][3])
                         : "r"(a0), "r"(a1), "r"(a2), "r"(a3), "r"(b2), "r"(b3));
        }
    }

    // epilogue: scale by dinv, fp16 store (y rows)
    const int group = lane >> 2, t4 = lane & 3;
    const int r0g = base + m_base + group;
    const int r1g = r0g + 8;
    const float dv0 = Dv[m_base + group];
    const float dv1 = Dv[m_base + group + 8];
#pragma unroll
    for (int nt = 0; nt < 4; nt++) {
        int ncol = n_base + nt * 8 + t4 * 2;
        if (r0g < N_NODES)
            *(__half2*)&g_xwh[(long)r0g * 64 + ncol] =
                __floats2half2_rn(d[nt][0] * dv0, d[nt][1] * dv0);
        if (r1g < N_NODES)
            *(__half2*)&g_xwh[(long)r1g * 64 + ncol] =
                __floats2half2_rn(d[nt][2] * dv1, d[nt][3] * dv1);
    }
}

// ---------------- pooling (sorted batch, run-length flush, 32-node chunks)
__global__ void k_pool(const float* __restrict__ b4, const int* __restrict__ batch) {
    int j = threadIdx.x & 63;
    int y = threadIdx.x >> 6;
    int start = blockIdx.x * 128 + y * 32;
    int end   = min(start + 32, N_NODES);
    if (start >= end) return;

    float bj = b4[j];
    int   curg = batch[start];
    float mx = 0.f, sm = 0.f;
    int   cnt = 0;

    for (int n = start; n < end; n++) {
        int g = batch[n];
        if (g != curg) {
            atomicMax((int*)&g_gmax[curg * 64 + j], __float_as_int(mx));
            atomicAdd(&g_gsum[curg * 64 + j], sm);
            if (j == 0) atomicAdd(&g_gcnt[curg], (float)cnt);
            curg = g; mx = 0.f; sm = 0.f; cnt = 0;
        }
        float v = fmaxf(g_agg[(long)n * 64 + j] + bj, 0.0f);
        mx = fmaxf(mx, v);
        sm += v;
        cnt++;
    }
    atomicMax((int*)&g_gmax[curg * 64 + j], __float_as_int(mx));
    atomicAdd(&g_gsum[curg * 64 + j], sm);
    if (j == 0) atomicAdd(&g_gcnt[curg], (float)cnt);
}

// ---------------- head ----------------------------------------------------
__global__ void k_head(const float* __restrict__ Wo, const float* __restrict__ bo,
                       float* __restrict__ out, int write_hg) {
    int g = blockIdx.x;
    int j = threadIdx.x;  // 0..127
    float cnt = fmaxf(g_gcnt[g], 1.0f);
    float val = (j < 64) ? g_gmax[g * 64 + j] : g_gsum[g * 64 + (j - 64)] / cnt;
    if (write_hg) out[N_GRAPHS + (long)g * 128 + j] = val;

    float p = val * Wo[j];
#pragma unroll
    for (int off = 16; off > 0; off >>= 1)
        p += __shfl_down_sync(0xffffffff, p, off);

    __shared__ float red[4];
    if ((j & 31) == 0) red[j >> 5] = p;
    __syncthreads();
    if (j == 0) out[g] = red[0] + red[1] + red[2] + red[3] + bo[0];
}

// ---------------- launch ---------------------------------------------------
extern "C" void kernel_launch(void* const* d_in, const int* in_sizes, int n_in,
                              void* d_out, int out_size) {
    const float* x     = (const float*)d_in[0];
    const int*   ei    = (const int*)  d_in[1];   // [2, E]
    const int*   batch = (const int*)  d_in[2];
    const float* W1 = (const float*)d_in[3];  const float* b1 = (const float*)d_in[4];
    const float* W2 = (const float*)d_in[5];  const float* b2 = (const float*)d_in[6];
    const float* W3 = (const float*)d_in[7];  const float* b3 = (const float*)d_in[8];
    const float* W4 = (const float*)d_in[9];  const float* b4 = (const float*)d_in[10];
    const float* Wo = (const float*)d_in[11]; const float* bo = (const float*)d_in[12];

    const int* rows = ei;            // source
    const int* cols = ei + N_EDGES;  // target

    float* out = (float*)d_out;
    int write_hg = (out_size >= N_GRAPHS + N_GRAPHS * 2 * HDIM) ? 1 : 0;

    const int NB_N  = (N_NODES + 255) / 256;
    const int NB_E4 = (N_EDGES / 4 + 255) / 256;

    // bucket CSR build (g_cnt arrives zeroed from previous call / load init)
    k_fill<<<NB_E4, 256>>>(rows, cols);
    k_prep<<<NB_N, 256>>>(x);

    const int L1_BLKS  = (N_NODES + 127) / 128;          // 782
    const int GT_BLKS  = (N_NODES + 63) / 64;            // 1563
    const int G64_BLKS = (N_NODES * 32 + 255) / 256;     // 12500

    // layer 1: fused 8-dim gather + GEMM + bias/relu -> g_aggh (h1, fp16)
    k_l1<<<L1_BLKS, 256>>>(W1, b1);
    // layers 2..4: y = dinv*(h @ W) fp16, gather -> h_{l+1} (or preact4 fp32)
    k_gemmT<<<GT_BLKS, 256>>>(W2);
    k_gather64_h<<<G64_BLKS, 256>>>(b2);           // g_aggh = h2
    k_gemmT<<<GT_BLKS, 256>>>(W3);
    k_gather64_h<<<G64_BLKS, 256>>>(b3);           // g_aggh = h3
    k_gemmT<<<GT_BLKS, 256>>>(W4);
    k_gather64_f<<<G64_BLKS, 256>>>();             // g_agg = preact4 (fp32)

    // pooling + head (relu(+b4) fused in pool)
    k_pool<<<(N_NODES + 127) / 128, 256>>>(b4, batch);
    k_head<<<N_GRAPHS, 128>>>(Wo, bo, out, write_hg);
}

// round 14
// speedup vs baseline: 1.5284x; 1.5284x over previous
#include <cuda_runtime.h>
#include <cuda_fp16.h>
#include <cuda_bf16.h>
#include <cstdint>

#define N_NODES 100000
#define N_EDGES 1000000
#define N_GRAPHS 512
#define HDIM 64
#define SCAN_B 1024
#define SCAN_NB ((N_NODES + SCAN_B - 1) / SCAN_B)   // 98

// ---------------- scratch (device globals; never passed from host) --------
__device__ __align__(16) float  g_dinv[N_NODES];
__device__ __align__(16) int    g_deg [N_NODES];
__device__ __align__(16) int    g_off [N_NODES + 1];
__device__ __align__(16) int    g_cur [N_NODES];
__device__ __align__(16) int    g_bsum[SCAN_NB];
__device__ __align__(16) int    g_csri[N_EDGES];          // src index only
__device__ __align__(16) float  g_xs  [N_NODES * 8];      // dinv[n]*x[n]
__device__ __align__(16) __half g_xwh [N_NODES * HDIM];   // y = dinv*xw (fp16)
__device__ __align__(16) __half g_aggh[N_NODES * HDIM];   // h = relu(preact+b) fp16
__device__ __align__(16) float  g_agg [N_NODES * HDIM];   // fp32 preact4 (for pool)
__device__ __align__(16) float  g_gmax[N_GRAPHS * HDIM];
__device__ __align__(16) float  g_gsum[N_GRAPHS * HDIM];
__device__ float g_gcnt[N_GRAPHS];

__device__ __forceinline__ uint32_t smem_u32(const void* p) {
    return (uint32_t)__cvta_generic_to_shared(p);
}

// ---------------- degree count (4 edges/thread) ---------------------------
__global__ void k_deg_count(const int* __restrict__ col) {
    int q = blockIdx.x * blockDim.x + threadIdx.x;
    if (q >= N_EDGES / 4) return;
    int4 c4 = ((const int4*)col)[q];
    atomicAdd(&g_deg[c4.x], 1);
    atomicAdd(&g_deg[c4.y], 1);
    atomicAdd(&g_deg[c4.z], 1);
    atomicAdd(&g_deg[c4.w], 1);
}

// ---------------- scan stage 1: per-chunk scan + dinv + deg self-zero -----
__global__ void k_scan1() {   // grid SCAN_NB, block 1024
    __shared__ int sh[SCAN_B];
    int idx = threadIdx.x;
    int n = blockIdx.x * SCAN_B + idx;
    int v = 0;
    if (n < N_NODES) {
        v = g_deg[n];
        g_deg[n] = 0;                          // clean for next call
        g_dinv[n] = rsqrtf((float)(v + 1));    // +1 self-loop
    }
    sh[idx] = v;
    __syncthreads();
#pragma unroll
    for (int d = 1; d < SCAN_B; d <<= 1) {
        int t = (idx >= d) ? sh[idx - d] : 0;
        __syncthreads();
        sh[idx] += t;
        __syncthreads();
    }
    if (n < N_NODES) g_off[n] = sh[idx] - v;          // exclusive (local)
    if (idx == SCAN_B - 1) g_bsum[blockIdx.x] = sh[idx];
}

// ---------------- scan stage 2: apply chunk prefixes + init g_cur +
// zero pooling buffers + pre-scale x rows (g_xs = dinv*x) ------------------
__global__ void k_scan3(const float* __restrict__ x) {
    __shared__ int sh[128];
    int t = threadIdx.x;
    int v = 0;
    if (t < 128) {
        v = (t < SCAN_NB) ? g_bsum[t] : 0;
        sh[t] = v;
    }
    __syncthreads();
#pragma unroll
    for (int d = 1; d < 128; d <<= 1) {
        int u = 0;
        if (t < 128 && t >= d) u = sh[t - d];
        __syncthreads();
        if (t < 128) sh[t] += u;
        __syncthreads();
    }
    if (t < 128) sh[t] -= v;   // exclusive chunk prefix
    __syncthreads();

    int n = blockIdx.x * 256 + t;
    if (n < N_NODES) {
        int o = g_off[n] + sh[n >> 10];
        g_off[n] = o;
        g_cur[n] = o;
        float dv = g_dinv[n];
        float4 a = ((const float4*)x)[(long)n * 2];
        float4 b = ((const float4*)x)[(long)n * 2 + 1];
        a.x *= dv; a.y *= dv; a.z *= dv; a.w *= dv;
        b.x *= dv; b.y *= dv; b.z *= dv; b.w *= dv;
        ((float4*)g_xs)[(long)n * 2]     = a;
        ((float4*)g_xs)[(long)n * 2 + 1] = b;
    }
    if (n == 0) g_off[N_NODES] = N_EDGES;
    if (n < N_GRAPHS * HDIM) { g_gmax[n] = 0.0f; g_gsum[n] = 0.0f; }
    if (n < N_GRAPHS) g_gcnt[n] = 0.0f;
}

// ---------------- CSR fill: index only, 4 edges/thread --------------------
__global__ void k_fill(const int* __restrict__ rows, const int* __restrict__ cols) {
    int q = blockIdx.x * blockDim.x + threadIdx.x;
    if (q >= N_EDGES / 4) return;
    int4 r4 = ((const int4*)rows)[q];
    int4 c4 = ((const int4*)cols)[q];
    int s0 = atomicAdd(&g_cur[c4.x], 1);
    int s1 = atomicAdd(&g_cur[c4.y], 1);
    int s2 = atomicAdd(&g_cur[c4.z], 1);
    int s3 = atomicAdd(&g_cur[c4.w], 1);
    g_csri[s0] = r4.x;
    g_csri[s1] = r4.y;
    g_csri[s2] = r4.z;
    g_csri[s3] = r4.w;
}

// ---------------- layer 1 fused: g_aggh = relu((A_hat@x)@W1 + b1) fp16 ----
__global__ void k_l1(const float* __restrict__ W1, const float* __restrict__ b1) {
    __shared__ __align__(16) float W1s[8 * 64];
    __shared__ __align__(16) float A[128 * 8];
    const int tid  = threadIdx.x;
    const int nloc = tid >> 1;
    const int half = tid & 1;
    const int n    = blockIdx.x * 128 + nloc;

    for (int i = tid; i < 512; i += 256) W1s[i] = W1[i];

    if (n < N_NODES) {
        const float4* xs4 = (const float4*)g_xs;
        int o0 = g_off[n], o1 = g_off[n + 1];
        float4 acc = xs4[(long)n * 2 + half];   // own scaled row
        int i = o0;
        for (; i + 2 <= o1; i += 2) {
            int r0 = g_csri[i], r1 = g_csri[i + 1];
            float4 v0 = xs4[(long)r0 * 2 + half];
            float4 v1 = xs4[(long)r1 * 2 + half];
            acc.x += v0.x + v1.x; acc.y += v0.y + v1.y;
            acc.z += v0.z + v1.z; acc.w += v0.w + v1.w;
        }
        if (i < o1) {
            float4 v0 = xs4[(long)g_csri[i] * 2 + half];
            acc.x += v0.x; acc.y += v0.y; acc.z += v0.z; acc.w += v0.w;
        }
        float dv = g_dinv[n];
        acc.x *= dv; acc.y *= dv; acc.z *= dv; acc.w *= dv;
        *(float4*)&A[nloc * 8 + half * 4] = acc;
    }
    __syncthreads();

    if (n < N_NODES) {
        float a[8];
        *(float4*)&a[0] = *(const float4*)&A[nloc * 8];
        *(float4*)&a[4] = *(const float4*)&A[nloc * 8 + 4];
        const int jc0 = half * 32;
        float4 acc[8];
#pragma unroll
        for (int g = 0; g < 8; g++) acc[g] = make_float4(0.f, 0.f, 0.f, 0.f);
#pragma unroll
        for (int k = 0; k < 8; k++) {
            float ak = a[k];
#pragma unroll
            for (int g = 0; g < 8; g++) {
                float4 w = *(const float4*)&W1s[k * 64 + jc0 + g * 4];
                acc[g].x = fmaf(ak, w.x, acc[g].x);
                acc[g].y = fmaf(ak, w.y, acc[g].y);
                acc[g].z = fmaf(ak, w.z, acc[g].z);
                acc[g].w = fmaf(ak, w.w, acc[g].w);
            }
        }
        // epilogue: h1 = relu(preact1 + b1) -> fp16
#pragma unroll
        for (int g = 0; g < 8; g++) {
            int j = jc0 + g * 4;
            float4 bb = *(const float4*)&b1[j];
            __half2 p0 = __floats2half2_rn(fmaxf(acc[g].x + bb.x, 0.f),
                                           fmaxf(acc[g].y + bb.y, 0.f));
            __half2 p1 = __floats2half2_rn(fmaxf(acc[g].z + bb.z, 0.f),
                                           fmaxf(acc[g].w + bb.w, 0.f));
            __half2 pair[2] = {p0, p1};
            *(uint2*)&g_aggh[(long)n * 64 + j] = *(uint2*)pair;
        }
    }
}

// ---------------- gather64_h: g_aggh = relu(dinv*(y[c]+sum y[r]) + b) fp16
__global__ void k_gather64_h(const float* __restrict__ bias) {
    int gwid = (blockIdx.x * blockDim.x + threadIdx.x) >> 5;
    int lane = threadIdx.x & 31;
    if (gwid >= N_NODES) return;
    const __half2* __restrict__ xw2 = (const __half2*)g_xwh;
    int o0 = g_off[gwid], o1 = g_off[gwid + 1];
    float2 acc = __half22float2(xw2[(long)gwid * 32 + lane]);  // own y row
    int i = o0;
    for (; i + 4 <= o1; i += 4) {
        int r0 = g_csri[i], r1 = g_csri[i + 1], r2 = g_csri[i + 2], r3 = g_csri[i + 3];
        float2 v0 = __half22float2(xw2[(long)r0 * 32 + lane]);
        float2 v1 = __half22float2(xw2[(long)r1 * 32 + lane]);
        float2 v2 = __half22float2(xw2[(long)r2 * 32 + lane]);
        float2 v3 = __half22float2(xw2[(long)r3 * 32 + lane]);
        acc.x += v0.x + v1.x; acc.y += v0.y + v1.y;
        acc.x += v2.x + v3.x; acc.y += v2.y + v3.y;
    }
    for (; i < o1; i++) {
        float2 v0 = __half22float2(xw2[(long)g_csri[i] * 32 + lane]);
        acc.x += v0.x; acc.y += v0.y;
    }
    float dv = g_dinv[gwid];
    float2 bb = *(const float2*)&bias[lane * 2];
    ((__half2*)g_aggh)[(long)gwid * 32 + lane] =
        __floats2half2_rn(fmaxf(acc.x * dv + bb.x, 0.f),
                          fmaxf(acc.y * dv + bb.y, 0.f));
}

// ---------------- gather64_f: g_agg = dinv*(y[c]+sum y[r]) fp32 (final) ---
__global__ void k_gather64_f() {
    int gwid = (blockIdx.x * blockDim.x + threadIdx.x) >> 5;
    int lane = threadIdx.x & 31;
    if (gwid >= N_NODES) return;
    const __half2* __restrict__ xw2 = (const __half2*)g_xwh;
    int o0 = g_off[gwid], o1 = g_off[gwid + 1];
    float2 acc = __half22float2(xw2[(long)gwid * 32 + lane]);
    int i = o0;
    for (; i + 4 <= o1; i += 4) {
        int r0 = g_csri[i], r1 = g_csri[i + 1], r2 = g_csri[i + 2], r3 = g_csri[i + 3];
        float2 v0 = __half22float2(xw2[(long)r0 * 32 + lane]);
        float2 v1 = __half22float2(xw2[(long)r1 * 32 + lane]);
        float2 v2 = __half22float2(xw2[(long)r2 * 32 + lane]);
        float2 v3 = __half22float2(xw2[(long)r3 * 32 + lane]);
        acc.x += v0.x + v1.x; acc.y += v0.y + v1.y;
        acc.x += v2.x + v3.x; acc.y += v2.y + v3.y;
    }
    for (; i < o1; i++) {
        float2 v0 = __half22float2(xw2[(long)g_csri[i] * 32 + lane]);
        acc.x += v0.x; acc.y += v0.y;
    }
    float dv = g_dinv[gwid];
    acc.x *= dv; acc.y *= dv;
    ((float2*)g_agg)[(long)gwid * 32 + lane] = acc;
}

// ---------------- GEMM K=64 tensor cores: g_xwh = dinv * (g_aggh @ W) -----
__global__ __launch_bounds__(256) void k_gemmT(const float* __restrict__ W) {
    __shared__ __align__(16) __half Sh[64 * 72];  // A fp16
    __shared__ __align__(16) __half Wh[64 * 72];  // W fp16
    __shared__ float Dv[64];
    const int tid  = threadIdx.x;
    const int base = blockIdx.x * 64;

    if (tid < 64) {
        int row = base + tid;
        Dv[tid] = (row < N_NODES) ? g_dinv[row] : 0.0f;
    }
    // stage A: copy fp16 rows
    for (int i = tid; i < 1024; i += 256) {
        int r = i >> 4, k4 = i & 15;
        int row = base + r;
        uint2 v = make_uint2(0u, 0u);
        if (row < N_NODES) v = *(const uint2*)&g_aggh[(long)row * 64 + k4 * 4];
        *(uint2*)&Sh[r * 72 + k4 * 4] = v;
    }
    // stage W -> fp16
    for (int i = tid; i < 2048; i += 256) {
        int k = i >> 5, j2 = i & 31;
        float2 w = *(const float2*)&W[k * 64 + j2 * 2];
        ((__half2*)Wh)[k * 36 + j2] = __floats2half2_rn(w.x, w.y);
    }
    __syncthreads();

    const int warp = tid >> 5, lane = tid & 31;
    const int m_base = (warp >> 1) * 16;
    const int n_base = (warp & 1) * 32;
    const int lt   = lane & 7;
    const int tile = lane >> 3;

    float d[4][4];
#pragma unroll
    for (int nt = 0; nt < 4; nt++)
#pragma unroll
        for (int q = 0; q < 4; q++) d[nt][q] = 0.f;

#pragma unroll
    for (int kc = 0; kc < 4; kc++) {
        int arow = m_base + lt + ((tile & 1) ? 8 : 0);
        int acol = kc * 16 + ((tile & 2) ? 8 : 0);
        uint32_t a0, a1, a2, a3;
        {
            uint32_t addr = smem_u32(&Sh[arow * 72 + acol]);
            asm volatile("ldmatrix.sync.aligned.m8n8.x4.shared.b16 {%0,%1,%2,%3}, [%4];"
                         : "=r"(a0), "=r"(a1), "=r"(a2), "=r"(a3) : "r"(addr));
        }
#pragma unroll
        for (int g = 0; g < 2; g++) {
            int krow = kc * 16 + lt + ((tile & 1) ? 8 : 0);
            int bcol = n_base + g * 16 + ((tile & 2) ? 8 : 0);
            uint32_t b0, b1, b2, b3;
            uint32_t addr = smem_u32(&Wh[krow * 72 + bcol]);
            asm volatile("ldmatrix.sync.aligned.m8n8.x4.trans.shared.b16 {%0,%1,%2,%3}, [%4];"
                         : "=r"(b0), "=r"(b1), "=r"(b2), "=r"(b3) : "r"(addr));
            asm volatile("mma.sync.aligned.m16n8k16.row.col.f32.f16.f16.f32 "
                         "{%0,%1,%2,%3},{%4,%5,%6,%7},{%8,%9},{%0,%1,%2,%3};"
                         : "+f"(d[g*2][0]), "+f"(d[g*2][1]), "+f"(d[g*2][2]), "+f"(d[g*2][3])
                         : "r"(a0), "r"(a1), "r"(a2), "r"(a3), "r"(b0), "r"(b1));
            asm volatile("mma.sync.aligned.m16n8k16.row.col.f32.f16.f16.f32 "
                         "{%0,%1,%2,%3},{%4,%5,%6,%7},{%8,%9},{%0,%1,%2,%3};"
                         : "+f"(d[g*2+1][0]), "+f"(d[g*2+1][1]), "+f"(d[g*2+1][2]), "+f"(d[g*2+1][3])
                         : "r"(a0), "r"(a1), "r"(a2), "r"(a3), "r"(b2), "r"(b3));
        }
    }

    // epilogue: scale by dinv, fp16 store (y rows)
    const int group = lane >> 2, t4 = lane & 3;
    const int r0g = base + m_base + group;
    const int r1g = r0g + 8;
    const float dv0 = Dv[m_base + group];
    const float dv1 = Dv[m_base + group + 8];
#pragma unroll
    for (int nt = 0; nt < 4; nt++) {
        int ncol = n_base + nt * 8 + t4 * 2;
        if (r0g < N_NODES)
            *(__half2*)&g_xwh[(long)r0g * 64 + ncol] =
                __floats2half2_rn(d[nt][0] * dv0, d[nt][1] * dv0);
        if (r1g < N_NODES)
            *(__half2*)&g_xwh[(long)r1g * 64 + ncol] =
                __floats2half2_rn(d[nt][2] * dv1, d[nt][3] * dv1);
    }
}

// ---------------- pooling (sorted batch, run-length flush, 32-node chunks)
__global__ void k_pool(const float* __restrict__ b4, const int* __restrict__ batch) {
    int j = threadIdx.x & 63;
    int y = threadIdx.x >> 6;
    int start = blockIdx.x * 128 + y * 32;
    int end   = min(start + 32, N_NODES);
    if (start >= end) return;

    float bj = b4[j];
    int   curg = batch[start];
    float mx = 0.f, sm = 0.f;
    int   cnt = 0;

    for (int n = start; n < end; n++) {
        int g = batch[n];
        if (g != curg) {
            atomicMax((int*)&g_gmax[curg * 64 + j], __float_as_int(mx));
            atomicAdd(&g_gsum[curg * 64 + j], sm);
            if (j == 0) atomicAdd(&g_gcnt[curg], (float)cnt);
            curg = g; mx = 0.f; sm = 0.f; cnt = 0;
        }
        float v = fmaxf(g_agg[(long)n * 64 + j] + bj, 0.0f);
        mx = fmaxf(mx, v);
        sm += v;
        cnt++;
    }
    atomicMax((int*)&g_gmax[curg * 64 + j], __float_as_int(mx));
    atomicAdd(&g_gsum[curg * 64 + j], sm);
    if (j == 0) atomicAdd(&g_gcnt[curg], (float)cnt);
}

// ---------------- head ----------------------------------------------------
__global__ void k_head(const float* __restrict__ Wo, const float* __restrict__ bo,
                       float* __restrict__ out, int write_hg) {
    int g = blockIdx.x;
    int j = threadIdx.x;  // 0..127
    float cnt = fmaxf(g_gcnt[g], 1.0f);
    float val = (j < 64) ? g_gmax[g * 64 + j] : g_gsum[g * 64 + (j - 64)] / cnt;
    if (write_hg) out[N_GRAPHS + (long)g * 128 + j] = val;

    float p = val * Wo[j];
#pragma unroll
    for (int off = 16; off > 0; off >>= 1)
        p += __shfl_down_sync(0xffffffff, p, off);

    __shared__ float red[4];
    if ((j & 31) == 0) red[j >> 5] = p;
    __syncthreads();
    if (j == 0) out[g] = red[0] + red[1] + red[2] + red[3] + bo[0];
}

// ---------------- launch ---------------------------------------------------
extern "C" void kernel_launch(void* const* d_in, const int* in_sizes, int n_in,
                              void* d_out, int out_size) {
    const float* x     = (const float*)d_in[0];
    const int*   ei    = (const int*)  d_in[1];   // [2, E]
    const int*   batch = (const int*)  d_in[2];
    const float* W1 = (const float*)d_in[3];  const float* b1 = (const float*)d_in[4];
    const float* W2 = (const float*)d_in[5];  const float* b2 = (const float*)d_in[6];
    const float* W3 = (const float*)d_in[7];  const float* b3 = (const float*)d_in[8];
    const float* W4 = (const float*)d_in[9];  const float* b4 = (const float*)d_in[10];
    const float* Wo = (const float*)d_in[11]; const float* bo = (const float*)d_in[12];

    const int* rows = ei;            // source
    const int* cols = ei + N_EDGES;  // target

    float* out = (float*)d_out;
    int write_hg = (out_size >= N_GRAPHS + N_GRAPHS * 2 * HDIM) ? 1 : 0;

    const int NB_N  = (N_NODES + 255) / 256;
    const int NB_E4 = (N_EDGES / 4 + 255) / 256;

    // CSR build (g_deg arrives zeroed from previous call / load-time init)
    k_deg_count<<<NB_E4, 256>>>(cols);
    k_scan1    <<<SCAN_NB, SCAN_B>>>();
    k_scan3    <<<NB_N, 256>>>(x);
    k_fill     <<<NB_E4, 256>>>(rows, cols);

    const int L1_BLKS  = (N_NODES + 127) / 128;          // 782
    const int GT_BLKS  = (N_NODES + 63) / 64;            // 1563
    const int G64_BLKS = (N_NODES * 32 + 255) / 256;     // 12500

    // layer 1: fused 8-dim gather + GEMM + bias/relu -> g_aggh (h1, fp16)
    k_l1<<<L1_BLKS, 256>>>(W1, b1);
    // layers 2..4: y = dinv*(h @ W) fp16, gather -> h_{l+1} (or preact4 fp32)
    k_gemmT<<<GT_BLKS, 256>>>(W2);
    k_gather64_h<<<G64_BLKS, 256>>>(b2);           // g_aggh = h2
    k_gemmT<<<GT_BLKS, 256>>>(W3);
    k_gather64_h<<<G64_BLKS, 256>>>(b3);           // g_aggh = h3
    k_gemmT<<<GT_BLKS, 256>>>(W4);
    k_gather64_f<<<G64_BLKS, 256>>>();             // g_agg = preact4 (fp32)

    // pooling + head (relu(+b4) fused in pool)
    k_pool<<<(N_NODES + 127) / 128, 256>>>(b4, batch);
    k_head<<<N_GRAPHS, 128>>>(Wo, bo, out, write_hg);
}

// round 15
// speedup vs baseline: 1.5650x; 1.0239x over previous
#include <cuda_runtime.h>
#include <cuda_fp16.h>
#include <cuda_bf16.h>
#include <cstdint>

#define N_NODES 100000
#define N_EDGES 1000000
#define N_GRAPHS 512
#define HDIM 64
#define SCAN_B 1024
#define SCAN_NB ((N_NODES + SCAN_B - 1) / SCAN_B)   // 98

// ---------------- scratch (device globals; never passed from host) --------
__device__ __align__(16) float  g_dinv[N_NODES];
__device__ __align__(16) int    g_deg [N_NODES];
__device__ __align__(16) int    g_off [N_NODES + 1];
__device__ __align__(16) int    g_cur [N_NODES];
__device__ __align__(16) int    g_bsum[SCAN_NB];
__device__ __align__(16) int    g_csri[N_EDGES];          // src index only
__device__ __align__(16) float  g_xs  [N_NODES * 8];      // dinv[n]*x[n]
__device__ __align__(16) __half g_xwh [N_NODES * HDIM];   // y = dinv*xw (fp16)
__device__ __align__(16) __half g_aggh[N_NODES * HDIM];   // h = relu(preact+b) fp16
__device__ __align__(16) float  g_agg [N_NODES * HDIM];   // fp32 preact4 (for pool)
__device__ __align__(16) float  g_gmax[N_GRAPHS * HDIM];
__device__ __align__(16) float  g_gsum[N_GRAPHS * HDIM];
__device__ float g_gcnt[N_GRAPHS];

__device__ __forceinline__ uint32_t smem_u32(const void* p) {
    return (uint32_t)__cvta_generic_to_shared(p);
}

// ---------------- degree count (4 edges/thread) ---------------------------
__global__ void k_deg_count(const int* __restrict__ col) {
    int q = blockIdx.x * blockDim.x + threadIdx.x;
    if (q >= N_EDGES / 4) return;
    int4 c4 = ((const int4*)col)[q];
    atomicAdd(&g_deg[c4.x], 1);
    atomicAdd(&g_deg[c4.y], 1);
    atomicAdd(&g_deg[c4.z], 1);
    atomicAdd(&g_deg[c4.w], 1);
}

// ---------------- scan stage 1: per-chunk scan + dinv + x-prescale +
// deg self-zero ------------------------------------------------------------
__global__ void k_scan1(const float* __restrict__ x) {   // grid SCAN_NB, block 1024
    __shared__ int sh[SCAN_B];
    int idx = threadIdx.x;
    int n = blockIdx.x * SCAN_B + idx;
    int v = 0;
    float dv = 0.0f;
    if (n < N_NODES) {
        v = g_deg[n];
        g_deg[n] = 0;                          // clean for next call
        dv = rsqrtf((float)(v + 1));           // +1 self-loop
        g_dinv[n] = dv;
    }
    sh[idx] = v;
    __syncthreads();
    // prescale x while the scan's smem latency plays out
    if (n < N_NODES) {
        float4 a = ((const float4*)x)[(long)n * 2];
        float4 b = ((const float4*)x)[(long)n * 2 + 1];
        a.x *= dv; a.y *= dv; a.z *= dv; a.w *= dv;
        b.x *= dv; b.y *= dv; b.z *= dv; b.w *= dv;
        ((float4*)g_xs)[(long)n * 2]     = a;
        ((float4*)g_xs)[(long)n * 2 + 1] = b;
    }
#pragma unroll
    for (int d = 1; d < SCAN_B; d <<= 1) {
        int t = (idx >= d) ? sh[idx - d] : 0;
        __syncthreads();
        sh[idx] += t;
        __syncthreads();
    }
    if (n < N_NODES) g_off[n] = sh[idx] - v;          // exclusive (local)
    if (idx == SCAN_B - 1) g_bsum[blockIdx.x] = sh[idx];
}

// ---------------- scan stage 2: apply chunk prefixes + init g_cur +
// zero pooling buffers -----------------------------------------------------
__global__ void k_scan3() {
    __shared__ int sh[128];
    int t = threadIdx.x;
    int v = 0;
    if (t < 128) {
        v = (t < SCAN_NB) ? g_bsum[t] : 0;
        sh[t] = v;
    }
    __syncthreads();
#pragma unroll
    for (int d = 1; d < 128; d <<= 1) {
        int u = 0;
        if (t < 128 && t >= d) u = sh[t - d];
        __syncthreads();
        if (t < 128) sh[t] += u;
        __syncthreads();
    }
    if (t < 128) sh[t] -= v;   // exclusive chunk prefix
    __syncthreads();

    int n = blockIdx.x * 256 + t;
    if (n < N_NODES) {
        int o = g_off[n] + sh[n >> 10];
        g_off[n] = o;
        g_cur[n] = o;
    }
    if (n == 0) g_off[N_NODES] = N_EDGES;
    if (n < N_GRAPHS * HDIM) { g_gmax[n] = 0.0f; g_gsum[n] = 0.0f; }
    if (n < N_GRAPHS) g_gcnt[n] = 0.0f;
}

// ---------------- CSR fill: index only, 4 edges/thread --------------------
__global__ void k_fill(const int* __restrict__ rows, const int* __restrict__ cols) {
    int q = blockIdx.x * blockDim.x + threadIdx.x;
    if (q >= N_EDGES / 4) return;
    int4 r4 = ((const int4*)rows)[q];
    int4 c4 = ((const int4*)cols)[q];
    int s0 = atomicAdd(&g_cur[c4.x], 1);
    int s1 = atomicAdd(&g_cur[c4.y], 1);
    int s2 = atomicAdd(&g_cur[c4.z], 1);
    int s3 = atomicAdd(&g_cur[c4.w], 1);
    g_csri[s0] = r4.x;
    g_csri[s1] = r4.y;
    g_csri[s2] = r4.z;
    g_csri[s3] = r4.w;
}

// ---------------- layer 1 fused: g_aggh = relu((A_hat@x)@W1 + b1) fp16 ----
__global__ void k_l1(const float* __restrict__ W1, const float* __restrict__ b1) {
    __shared__ __align__(16) float W1s[8 * 64];
    __shared__ __align__(16) float A[128 * 8];
    const int tid  = threadIdx.x;
    const int nloc = tid >> 1;
    const int half = tid & 1;
    const int n    = blockIdx.x * 128 + nloc;

    for (int i = tid; i < 512; i += 256) W1s[i] = W1[i];

    if (n < N_NODES) {
        const float4* xs4 = (const float4*)g_xs;
        int o0 = g_off[n], o1 = g_off[n + 1];
        float4 acc = xs4[(long)n * 2 + half];   // own scaled row
        int i = o0;
        for (; i + 4 <= o1; i += 4) {
            int r0 = g_csri[i], r1 = g_csri[i + 1];
            int r2 = g_csri[i + 2], r3 = g_csri[i + 3];
            float4 v0 = xs4[(long)r0 * 2 + half];
            float4 v1 = xs4[(long)r1 * 2 + half];
            float4 v2 = xs4[(long)r2 * 2 + half];
            float4 v3 = xs4[(long)r3 * 2 + half];
            acc.x += (v0.x + v1.x) + (v2.x + v3.x);
            acc.y += (v0.y + v1.y) + (v2.y + v3.y);
            acc.z += (v0.z + v1.z) + (v2.z + v3.z);
            acc.w += (v0.w + v1.w) + (v2.w + v3.w);
        }
        for (; i < o1; i++) {
            float4 v0 = xs4[(long)g_csri[i] * 2 + half];
            acc.x += v0.x; acc.y += v0.y; acc.z += v0.z; acc.w += v0.w;
        }
        float dv = g_dinv[n];
        acc.x *= dv; acc.y *= dv; acc.z *= dv; acc.w *= dv;
        *(float4*)&A[nloc * 8 + half * 4] = acc;
    }
    __syncthreads();

    if (n < N_NODES) {
        float a[8];
        *(float4*)&a[0] = *(const float4*)&A[nloc * 8];
        *(float4*)&a[4] = *(const float4*)&A[nloc * 8 + 4];
        const int jc0 = half * 32;
        float4 acc[8];
#pragma unroll
        for (int g = 0; g < 8; g++) acc[g] = make_float4(0.f, 0.f, 0.f, 0.f);
#pragma unroll
        for (int k = 0; k < 8; k++) {
            float ak = a[k];
#pragma unroll
            for (int g = 0; g < 8; g++) {
                float4 w = *(const float4*)&W1s[k * 64 + jc0 + g * 4];
                acc[g].x = fmaf(ak, w.x, acc[g].x);
                acc[g].y = fmaf(ak, w.y, acc[g].y);
                acc[g].z = fmaf(ak, w.z, acc[g].z);
                acc[g].w = fmaf(ak, w.w, acc[g].w);
            }
        }
        // epilogue: h1 = relu(preact1 + b1) -> fp16
#pragma unroll
        for (int g = 0; g < 8; g++) {
            int j = jc0 + g * 4;
            float4 bb = *(const float4*)&b1[j];
            __half2 p0 = __floats2half2_rn(fmaxf(acc[g].x + bb.x, 0.f),
                                           fmaxf(acc[g].y + bb.y, 0.f));
            __half2 p1 = __floats2half2_rn(fmaxf(acc[g].z + bb.z, 0.f),
                                           fmaxf(acc[g].w + bb.w, 0.f));
            __half2 pair[2] = {p0, p1};
            *(uint2*)&g_aggh[(long)n * 64 + j] = *(uint2*)pair;
        }
    }
}

// ---------------- gather64_h: g_aggh = relu(dinv*(y[c]+sum y[r]) + b) fp16
// Warp per node; unroll 8 for MLP.
__global__ void k_gather64_h(const float* __restrict__ bias) {
    int gwid = (blockIdx.x * blockDim.x + threadIdx.x) >> 5;
    int lane = threadIdx.x & 31;
    if (gwid >= N_NODES) return;
    const __half2* __restrict__ xw2 = (const __half2*)g_xwh;
    int o0 = g_off[gwid], o1 = g_off[gwid + 1];
    float2 acc = __half22float2(xw2[(long)gwid * 32 + lane]);  // own y row
    int i = o0;
    for (; i + 8 <= o1; i += 8) {
        int r0 = g_csri[i],     r1 = g_csri[i + 1], r2 = g_csri[i + 2], r3 = g_csri[i + 3];
        int r4 = g_csri[i + 4], r5 = g_csri[i + 5], r6 = g_csri[i + 6], r7 = g_csri[i + 7];
        float2 v0 = __half22float2(xw2[(long)r0 * 32 + lane]);
        float2 v1 = __half22float2(xw2[(long)r1 * 32 + lane]);
        float2 v2 = __half22float2(xw2[(long)r2 * 32 + lane]);
        float2 v3 = __half22float2(xw2[(long)r3 * 32 + lane]);
        float2 v4 = __half22float2(xw2[(long)r4 * 32 + lane]);
        float2 v5 = __half22float2(xw2[(long)r5 * 32 + lane]);
        float2 v6 = __half22float2(xw2[(long)r6 * 32 + lane]);
        float2 v7 = __half22float2(xw2[(long)r7 * 32 + lane]);
        acc.x += ((v0.x + v1.x) + (v2.x + v3.x)) + ((v4.x + v5.x) + (v6.x + v7.x));
        acc.y += ((v0.y + v1.y) + (v2.y + v3.y)) + ((v4.y + v5.y) + (v6.y + v7.y));
    }
    for (; i + 4 <= o1; i += 4) {
        int r0 = g_csri[i], r1 = g_csri[i + 1], r2 = g_csri[i + 2], r3 = g_csri[i + 3];
        float2 v0 = __half22float2(xw2[(long)r0 * 32 + lane]);
        float2 v1 = __half22float2(xw2[(long)r1 * 32 + lane]);
        float2 v2 = __half22float2(xw2[(long)r2 * 32 + lane]);
        float2 v3 = __half22float2(xw2[(long)r3 * 32 + lane]);
        acc.x += (v0.x + v1.x) + (v2.x + v3.x);
        acc.y += (v0.y + v1.y) + (v2.y + v3.y);
    }
    for (; i < o1; i++) {
        float2 v0 = __half22float2(xw2[(long)g_csri[i] * 32 + lane]);
        acc.x += v0.x; acc.y += v0.y;
    }
    float dv = g_dinv[gwid];
    float2 bb = *(const float2*)&bias[lane * 2];
    ((__half2*)g_aggh)[(long)gwid * 32 + lane] =
        __floats2half2_rn(fmaxf(acc.x * dv + bb.x, 0.f),
                          fmaxf(acc.y * dv + bb.y, 0.f));
}

// ---------------- gather64_f: g_agg = dinv*(y[c]+sum y[r]) fp32 (final) ---
__global__ void k_gather64_f() {
    int gwid = (blockIdx.x * blockDim.x + threadIdx.x) >> 5;
    int lane = threadIdx.x & 31;
    if (gwid >= N_NODES) return;
    const __half2* __restrict__ xw2 = (const __half2*)g_xwh;
    int o0 = g_off[gwid], o1 = g_off[gwid + 1];
    float2 acc = __half22float2(xw2[(long)gwid * 32 + lane]);
    int i = o0;
    for (; i + 8 <= o1; i += 8) {
        int r0 = g_csri[i],     r1 = g_csri[i + 1], r2 = g_csri[i + 2], r3 = g_csri[i + 3];
        int r4 = g_csri[i + 4], r5 = g_csri[i + 5], r6 = g_csri[i + 6], r7 = g_csri[i + 7];
        float2 v0 = __half22float2(xw2[(long)r0 * 32 + lane]);
        float2 v1 = __half22float2(xw2[(long)r1 * 32 + lane]);
        float2 v2 = __half22float2(xw2[(long)r2 * 32 + lane]);
        float2 v3 = __half22float2(xw2[(long)r3 * 32 + lane]);
        float2 v4 = __half22float2(xw2[(long)r4 * 32 + lane]);
        float2 v5 = __half22float2(xw2[(long)r5 * 32 + lane]);
        float2 v6 = __half22float2(xw2[(long)r6 * 32 + lane]);
        float2 v7 = __half22float2(xw2[(long)r7 * 32 + lane]);
        acc.x += ((v0.x + v1.x) + (v2.x + v3.x)) + ((v4.x + v5.x) + (v6.x + v7.x));
        acc.y += ((v0.y + v1.y) + (v2.y + v3.y)) + ((v4.y + v5.y) + (v6.y + v7.y));
    }
    for (; i + 4 <= o1; i += 4) {
        int r0 = g_csri[i], r1 = g_csri[i + 1], r2 = g_csri[i + 2], r3 = g_csri[i + 3];
        float2 v0 = __half22float2(xw2[(long)r0 * 32 + lane]);
        float2 v1 = __half22float2(xw2[(long)r1 * 32 + lane]);
        float2 v2 = __half22float2(xw2[(long)r2 * 32 + lane]);
        float2 v3 = __half22float2(xw2[(long)r3 * 32 + lane]);
        acc.x += (v0.x + v1.x) + (v2.x + v3.x);
        acc.y += (v0.y + v1.y) + (v2.y + v3.y);
    }
    for (; i < o1; i++) {
        float2 v0 = __half22float2(xw2[(long)g_csri[i] * 32 + lane]);
        acc.x += v0.x; acc.y += v0.y;
    }
    float dv = g_dinv[gwid];
    acc.x *= dv; acc.y *= dv;
    ((float2*)g_agg)[(long)gwid * 32 + lane] = acc;
}

// ---------------- GEMM K=64 tensor cores: g_xwh = dinv * (g_aggh @ W) -----
__global__ __launch_bounds__(256) void k_gemmT(const float* __restrict__ W) {
    __shared__ __align__(16) __half Sh[64 * 72];  // A fp16
    __shared__ __align__(16) __half Wh[64 * 72];  // W fp16
    __shared__ float Dv[64];
    const int tid  = threadIdx.x;
    const int base = blockIdx.x * 64;

    if (tid < 64) {
        int row = base + tid;
        Dv[tid] = (row < N_NODES) ? g_dinv[row] : 0.0f;
    }
    // stage A: copy fp16 rows
    for (int i = tid; i < 1024; i += 256) {
        int r = i >> 4, k4 = i & 15;
        int row = base + r;
        uint2 v = make_uint2(0u, 0u);
        if (row < N_NODES) v = *(const uint2*)&g_aggh[(long)row * 64 + k4 * 4];
        *(uint2*)&Sh[r * 72 + k4 * 4] = v;
    }
    // stage W -> fp16
    for (int i = tid; i < 2048; i += 256) {
        int k = i >> 5, j2 = i & 31;
        float2 w = *(const float2*)&W[k * 64 + j2 * 2];
        ((__half2*)Wh)[k * 36 + j2] = __floats2half2_rn(w.x, w.y);
    }
    __syncthreads();

    const int warp = tid >> 5, lane = tid & 31;
    const int m_base = (warp >> 1) * 16;
    const int n_base = (warp & 1) * 32;
    const int lt   = lane & 7;
    const int tile = lane >> 3;

    float d[4][4];
#pragma unroll
    for (int nt = 0; nt < 4; nt++)
#pragma unroll
        for (int q = 0; q < 4; q++) d[nt][q] = 0.f;

#pragma unroll
    for (int kc = 0; kc < 4; kc++) {
        int arow = m_base + lt + ((tile & 1) ? 8 : 0);
        int acol = kc * 16 + ((tile & 2) ? 8 : 0);
        uint32_t a0, a1, a2, a3;
        {
            uint32_t addr = smem_u32(&Sh[arow * 72 + acol]);
            asm volatile("ldmatrix.sync.aligned.m8n8.x4.shared.b16 {%0,%1,%2,%3}, [%4];"
                         : "=r"(a0), "=r"(a1), "=r"(a2), "=r"(a3) : "r"(addr));
        }
#pragma unroll
        for (int g = 0; g < 2; g++) {
            int krow = kc * 16 + lt + ((tile & 1) ? 8 : 0);
            int bcol = n_base + g * 16 + ((tile & 2) ? 8 : 0);
            uint32_t b0, b1, b2, b3;
            uint32_t addr = smem_u32(&Wh[krow * 72 + bcol]);
            asm volatile("ldmatrix.sync.aligned.m8n8.x4.trans.shared.b16 {%0,%1,%2,%3}, [%4];"
                         : "=r"(b0), "=r"(b1), "=r"(b2), "=r"(b3) : "r"(addr));
            asm volatile("mma.sync.aligned.m16n8k16.row.col.f32.f16.f16.f32 "
                         "{%0,%1,%2,%3},{%4,%5,%6,%7},{%8,%9},{%0,%1,%2,%3};"
                         : "+f"(d[g*2][0]), "+f"(d[g*2][1]), "+f"(d[g*2][2]), "+f"(d[g*2][3])
                         : "r"(a0), "r"(a1), "r"(a2), "r"(a3), "r"(b0), "r"(b1));
            asm volatile("mma.sync.aligned.m16n8k16.row.col.f32.f16.f16.f32 "
                         "{%0,%1,%2,%3},{%4,%5,%6,%7},{%8,%9},{%0,%1,%2,%3};"
                         : "+f"(d[g*2+1][0]), "+f"(d[g*2+1][1]), "+f"(d[g*2+1][2]), "+f"(d[g*2+1][3])
                         : "r"(a0), "r"(a1), "r"(a2), "r"(a3), "r"(b2), "r"(b3));
        }
    }

    // epilogue: scale by dinv, fp16 store (y rows)
    const int group = lane >> 2, t4 = lane & 3;
    const int r0g = base + m_base + group;
    const int r1g = r0g + 8;
    const float dv0 = Dv[m_base + group];
    const float dv1 = Dv[m_base + group + 8];
#pragma unroll
    for (int nt = 0; nt < 4; nt++) {
        int ncol = n_base + nt * 8 + t4 * 2;
        if (r0g < N_NODES)
            *(__half2*)&g_xwh[(long)r0g * 64 + ncol] =
                __floats2half2_rn(d[nt][0] * dv0, d[nt][1] * dv0);
        if (r1g < N_NODES)
            *(__half2*)&g_xwh[(long)r1g * 64 + ncol] =
                __floats2half2_rn(d[nt][2] * dv1, d[nt][3] * dv1);
    }
}

// ---------------- pooling (sorted batch, run-length flush, 32-node chunks)
__global__ void k_pool(const float* __restrict__ b4, const int* __restrict__ batch) {
    int j = threadIdx.x & 63;
    int y = threadIdx.x >> 6;
    int start = blockIdx.x * 128 + y * 32;
    int end   = min(start + 32, N_NODES);
    if (start >= end) return;

    float bj = b4[j];
    int   curg = batch[start];
    float mx = 0.f, sm = 0.f;
    int   cnt = 0;

    for (int n = start; n < end; n++) {
        int g = batch[n];
        if (g != curg) {
            atomicMax((int*)&g_gmax[curg * 64 + j], __float_as_int(mx));
            atomicAdd(&g_gsum[curg * 64 + j], sm);
            if (j == 0) atomicAdd(&g_gcnt[curg], (float)cnt);
            curg = g; mx = 0.f; sm = 0.f; cnt = 0;
        }
        float v = fmaxf(g_agg[(long)n * 64 + j] + bj, 0.0f);
        mx = fmaxf(mx, v);
        sm += v;
        cnt++;
    }
    atomicMax((int*)&g_gmax[curg * 64 + j], __float_as_int(mx));
    atomicAdd(&g_gsum[curg * 64 + j], sm);
    if (j == 0) atomicAdd(&g_gcnt[curg], (float)cnt);
}

// ---------------- head ----------------------------------------------------
__global__ void k_head(const float* __restrict__ Wo, const float* __restrict__ bo,
                       float* __restrict__ out, int write_hg) {
    int g = blockIdx.x;
    int j = threadIdx.x;  // 0..127
    float cnt = fmaxf(g_gcnt[g], 1.0f);
    float val = (j < 64) ? g_gmax[g * 64 + j] : g_gsum[g * 64 + (j - 64)] / cnt;
    if (write_hg) out[N_GRAPHS + (long)g * 128 + j] = val;

    float p = val * Wo[j];
#pragma unroll
    for (int off = 16; off > 0; off >>= 1)
        p += __shfl_down_sync(0xffffffff, p, off);

    __shared__ float red[4];
    if ((j & 31) == 0) red[j >> 5] = p;
    __syncthreads();
    if (j == 0) out[g] = red[0] + red[1] + red[2] + red[3] + bo[0];
}

// ---------------- launch ---------------------------------------------------
extern "C" void kernel_launch(void* const* d_in, const int* in_sizes, int n_in,
                              void* d_out, int out_size) {
    const float* x     = (const float*)d_in[0];
    const int*   ei    = (const int*)  d_in[1];   // [2, E]
    const int*   batch = (const int*)  d_in[2];
    const float* W1 = (const float*)d_in[3];  const float* b1 = (const float*)d_in[4];
    const float* W2 = (const float*)d_in[5];  const float* b2 = (const float*)d_in[6];
    const float* W3 = (const float*)d_in[7];  const float* b3 = (const float*)d_in[8];
    const float* W4 = (const float*)d_in[9];  const float* b4 = (const float*)d_in[10];
    const float* Wo = (const float*)d_in[11]; const float* bo = (const float*)d_in[12];

    const int* rows = ei;            // source
    const int* cols = ei + N_EDGES;  // target

    float* out = (float*)d_out;
    int write_hg = (out_size >= N_GRAPHS + N_GRAPHS * 2 * HDIM) ? 1 : 0;

    const int NB_N  = (N_NODES + 255) / 256;
    const int NB_E4 = (N_EDGES / 4 + 255) / 256;

    // CSR build (g_deg arrives zeroed from previous call / load-time init)
    k_deg_count<<<NB_E4, 256>>>(cols);
    k_scan1    <<<SCAN_NB, SCAN_B>>>(x);
    k_scan3    <<<NB_N, 256>>>();
    k_fill     <<<NB_E4, 256>>>(rows, cols);

    const int L1_BLKS  = (N_NODES + 127) / 128;          // 782
    const int GT_BLKS  = (N_NODES + 63) / 64;            // 1563
    const int G64_BLKS = (N_NODES * 32 + 255) / 256;     // 12500

    // layer 1: fused 8-dim gather + GEMM + bias/relu -> g_aggh (h1, fp16)
    k_l1<<<L1_BLKS, 256>>>(W1, b1);
    // layers 2..4: y = dinv*(h @ W) fp16, gather -> h_{l+1} (or preact4 fp32)
    k_gemmT<<<GT_BLKS, 256>>>(W2);
    k_gather64_h<<<G64_BLKS, 256>>>(b2);           // g_aggh = h2
    k_gemmT<<<GT_BLKS, 256>>>(W3);
    k_gather64_h<<<G64_BLKS, 256>>>(b3);           // g_aggh = h3
    k_gemmT<<<GT_BLKS, 256>>>(W4);
    k_gather64_f<<<G64_BLKS, 256>>>();             // g_agg = preact4 (fp32)

    // pooling + head (relu(+b4) fused in pool)
    k_pool<<<(N_NODES + 127) / 128, 256>>>(b4, batch);
    k_head<<<N_GRAPHS, 128>>>(Wo, bo, out, write_hg);
}

// round 16
// speedup vs baseline: 1.7561x; 1.1221x over previous
#include <cuda_runtime.h>
#include <cuda_fp16.h>
#include <cuda_bf16.h>
#include <cstdint>

#define N_NODES 100000
#define N_EDGES 1000000
#define N_GRAPHS 512
#define HDIM 64
#define SCAN_B 1024
#define SCAN_NB ((N_NODES + SCAN_B - 1) / SCAN_B)   // 98

// ---------------- scratch (device globals; never passed from host) --------
__device__ __align__(16) float  g_dinv[N_NODES];
__device__ __align__(16) int    g_deg [N_NODES];
__device__ __align__(16) int    g_off [N_NODES + 1];
__device__ __align__(16) int    g_cur [N_NODES];
__device__ __align__(16) int    g_bsum[SCAN_NB];
__device__ __align__(16) int    g_csri[N_EDGES];          // src index only
__device__ __align__(16) float  g_xs  [N_NODES * 8];      // dinv[n]*x[n]
__device__ __align__(16) __half g_xwh [N_NODES * HDIM];   // y = dinv*xw (fp16)
__device__ __align__(16) __half g_aggh[N_NODES * HDIM];   // h = relu(preact+b) fp16
__device__ __align__(16) float  g_agg [N_NODES * HDIM];   // fp32 preact4 (for pool)
__device__ __align__(16) float  g_gmax[N_GRAPHS * HDIM];
__device__ __align__(16) float  g_gsum[N_GRAPHS * HDIM];
__device__ float g_gcnt[N_GRAPHS];

__device__ __forceinline__ uint32_t smem_u32(const void* p) {
    return (uint32_t)__cvta_generic_to_shared(p);
}

// fp16x4 helpers (uint2 = 4 halves)
__device__ __forceinline__ float4 h4_to_f4(uint2 u) {
    float2 a = __half22float2(*(__half2*)&u.x);
    float2 b = __half22float2(*(__half2*)&u.y);
    return make_float4(a.x, a.y, b.x, b.y);
}

// ---------------- degree count (4 edges/thread) ---------------------------
__global__ void k_deg_count(const int* __restrict__ col) {
    int q = blockIdx.x * blockDim.x + threadIdx.x;
    if (q >= N_EDGES / 4) return;
    int4 c4 = ((const int4*)col)[q];
    atomicAdd(&g_deg[c4.x], 1);
    atomicAdd(&g_deg[c4.y], 1);
    atomicAdd(&g_deg[c4.z], 1);
    atomicAdd(&g_deg[c4.w], 1);
}

// ---------------- scan stage 1: per-chunk scan + dinv + x-prescale +
// deg self-zero ------------------------------------------------------------
__global__ void k_scan1(const float* __restrict__ x) {   // grid SCAN_NB, block 1024
    __shared__ int sh[SCAN_B];
    int idx = threadIdx.x;
    int n = blockIdx.x * SCAN_B + idx;
    int v = 0;
    float dv = 0.0f;
    if (n < N_NODES) {
        v = g_deg[n];
        g_deg[n] = 0;                          // clean for next call
        dv = rsqrtf((float)(v + 1));           // +1 self-loop
        g_dinv[n] = dv;
    }
    sh[idx] = v;
    __syncthreads();
    // prescale x while the scan's smem latency plays out
    if (n < N_NODES) {
        float4 a = ((const float4*)x)[(long)n * 2];
        float4 b = ((const float4*)x)[(long)n * 2 + 1];
        a.x *= dv; a.y *= dv; a.z *= dv; a.w *= dv;
        b.x *= dv; b.y *= dv; b.z *= dv; b.w *= dv;
        ((float4*)g_xs)[(long)n * 2]     = a;
        ((float4*)g_xs)[(long)n * 2 + 1] = b;
    }
#pragma unroll
    for (int d = 1; d < SCAN_B; d <<= 1) {
        int t = (idx >= d) ? sh[idx - d] : 0;
        __syncthreads();
        sh[idx] += t;
        __syncthreads();
    }
    if (n < N_NODES) g_off[n] = sh[idx] - v;          // exclusive (local)
    if (idx == SCAN_B - 1) g_bsum[blockIdx.x] = sh[idx];
}

// ---------------- scan stage 2: apply chunk prefixes + init g_cur +
// zero pooling buffers -----------------------------------------------------
__global__ void k_scan3() {
    __shared__ int sh[128];
    int t = threadIdx.x;
    int v = 0;
    if (t < 128) {
        v = (t < SCAN_NB) ? g_bsum[t] : 0;
        sh[t] = v;
    }
    __syncthreads();
#pragma unroll
    for (int d = 1; d < 128; d <<= 1) {
        int u = 0;
        if (t < 128 && t >= d) u = sh[t - d];
        __syncthreads();
        if (t < 128) sh[t] += u;
        __syncthreads();
    }
    if (t < 128) sh[t] -= v;   // exclusive chunk prefix
    __syncthreads();

    int n = blockIdx.x * 256 + t;
    if (n < N_NODES) {
        int o = g_off[n] + sh[n >> 10];
        g_off[n] = o;
        g_cur[n] = o;
    }
    if (n == 0) g_off[N_NODES] = N_EDGES;
    if (n < N_GRAPHS * HDIM) { g_gmax[n] = 0.0f; g_gsum[n] = 0.0f; }
    if (n < N_GRAPHS) g_gcnt[n] = 0.0f;
}

// ---------------- CSR fill: index only, 4 edges/thread --------------------
__global__ void k_fill(const int* __restrict__ rows, const int* __restrict__ cols) {
    int q = blockIdx.x * blockDim.x + threadIdx.x;
    if (q >= N_EDGES / 4) return;
    int4 r4 = ((const int4*)rows)[q];
    int4 c4 = ((const int4*)cols)[q];
    int s0 = atomicAdd(&g_cur[c4.x], 1);
    int s1 = atomicAdd(&g_cur[c4.y], 1);
    int s2 = atomicAdd(&g_cur[c4.z], 1);
    int s3 = atomicAdd(&g_cur[c4.w], 1);
    g_csri[s0] = r4.x;
    g_csri[s1] = r4.y;
    g_csri[s2] = r4.z;
    g_csri[s3] = r4.w;
}

// ---------------- layer 1 fused: g_aggh = relu((A_hat@x)@W1 + b1) fp16 ----
__global__ void k_l1(const float* __restrict__ W1, const float* __restrict__ b1) {
    __shared__ __align__(16) float W1s[8 * 64];
    __shared__ __align__(16) float A[128 * 8];
    const int tid  = threadIdx.x;
    const int nloc = tid >> 1;
    const int half = tid & 1;
    const int n    = blockIdx.x * 128 + nloc;

    for (int i = tid; i < 512; i += 256) W1s[i] = W1[i];

    if (n < N_NODES) {
        const float4* xs4 = (const float4*)g_xs;
        int o0 = g_off[n], o1 = g_off[n + 1];
        float4 acc = xs4[(long)n * 2 + half];   // own scaled row
        int i = o0;
        for (; i + 4 <= o1; i += 4) {
            int r0 = g_csri[i], r1 = g_csri[i + 1];
            int r2 = g_csri[i + 2], r3 = g_csri[i + 3];
            float4 v0 = xs4[(long)r0 * 2 + half];
            float4 v1 = xs4[(long)r1 * 2 + half];
            float4 v2 = xs4[(long)r2 * 2 + half];
            float4 v3 = xs4[(long)r3 * 2 + half];
            acc.x += (v0.x + v1.x) + (v2.x + v3.x);
            acc.y += (v0.y + v1.y) + (v2.y + v3.y);
            acc.z += (v0.z + v1.z) + (v2.z + v3.z);
            acc.w += (v0.w + v1.w) + (v2.w + v3.w);
        }
        for (; i < o1; i++) {
            float4 v0 = xs4[(long)g_csri[i] * 2 + half];
            acc.x += v0.x; acc.y += v0.y; acc.z += v0.z; acc.w += v0.w;
        }
        float dv = g_dinv[n];
        acc.x *= dv; acc.y *= dv; acc.z *= dv; acc.w *= dv;
        *(float4*)&A[nloc * 8 + half * 4] = acc;
    }
    __syncthreads();

    if (n < N_NODES) {
        float a[8];
        *(float4*)&a[0] = *(const float4*)&A[nloc * 8];
        *(float4*)&a[4] = *(const float4*)&A[nloc * 8 + 4];
        const int jc0 = half * 32;
        float4 acc[8];
#pragma unroll
        for (int g = 0; g < 8; g++) acc[g] = make_float4(0.f, 0.f, 0.f, 0.f);
#pragma unroll
        for (int k = 0; k < 8; k++) {
            float ak = a[k];
#pragma unroll
            for (int g = 0; g < 8; g++) {
                float4 w = *(const float4*)&W1s[k * 64 + jc0 + g * 4];
                acc[g].x = fmaf(ak, w.x, acc[g].x);
                acc[g].y = fmaf(ak, w.y, acc[g].y);
                acc[g].z = fmaf(ak, w.z, acc[g].z);
                acc[g].w = fmaf(ak, w.w, acc[g].w);
            }
        }
        // epilogue: h1 = relu(preact1 + b1) -> fp16
#pragma unroll
        for (int g = 0; g < 8; g++) {
            int j = jc0 + g * 4;
            float4 bb = *(const float4*)&b1[j];
            __half2 p0 = __floats2half2_rn(fmaxf(acc[g].x + bb.x, 0.f),
                                           fmaxf(acc[g].y + bb.y, 0.f));
            __half2 p1 = __floats2half2_rn(fmaxf(acc[g].z + bb.z, 0.f),
                                           fmaxf(acc[g].w + bb.w, 0.f));
            __half2 pair[2] = {p0, p1};
            *(uint2*)&g_aggh[(long)n * 64 + j] = *(uint2*)pair;
        }
    }
}

// ---------------- gather64_h: 2 nodes per warp, 16 lanes/node, uint2 lanes.
// g_aggh = relu(dinv*(y[c]+sum y[r]) + b) fp16
__global__ void k_gather64_h(const float* __restrict__ bias) {
    int t = blockIdx.x * blockDim.x + threadIdx.x;
    int lane = threadIdx.x & 31;
    int n = ((t >> 5) << 1) + (lane >> 4);    // 2 nodes per warp
    int l16 = lane & 15;                      // slice within node (16B granule)
    if (n >= N_NODES) return;
    const uint2* __restrict__ xw4 = (const uint2*)g_xwh;  // 4 halves per entry
    int o0 = g_off[n], o1 = g_off[n + 1];
    float4 acc = h4_to_f4(xw4[(long)n * 16 + l16]);       // own y row
    int i = o0;
    for (; i + 4 <= o1; i += 4) {
        int r0 = g_csri[i], r1 = g_csri[i + 1], r2 = g_csri[i + 2], r3 = g_csri[i + 3];
        float4 v0 = h4_to_f4(xw4[(long)r0 * 16 + l16]);
        float4 v1 = h4_to_f4(xw4[(long)r1 * 16 + l16]);
        float4 v2 = h4_to_f4(xw4[(long)r2 * 16 + l16]);
        float4 v3 = h4_to_f4(xw4[(long)r3 * 16 + l16]);
        acc.x += (v0.x + v1.x) + (v2.x + v3.x);
        acc.y += (v0.y + v1.y) + (v2.y + v3.y);
        acc.z += (v0.z + v1.z) + (v2.z + v3.z);
        acc.w += (v0.w + v1.w) + (v2.w + v3.w);
    }
    for (; i < o1; i++) {
        float4 v0 = h4_to_f4(xw4[(long)g_csri[i] * 16 + l16]);
        acc.x += v0.x; acc.y += v0.y; acc.z += v0.z; acc.w += v0.w;
    }
    float dv = g_dinv[n];
    float4 bb = *(const float4*)&bias[l16 * 4];
    __half2 p0 = __floats2half2_rn(fmaxf(acc.x * dv + bb.x, 0.f),
                                   fmaxf(acc.y * dv + bb.y, 0.f));
    __half2 p1 = __floats2half2_rn(fmaxf(acc.z * dv + bb.z, 0.f),
                                   fmaxf(acc.w * dv + bb.w, 0.f));
    __half2 pair[2] = {p0, p1};
    ((uint2*)g_aggh)[(long)n * 16 + l16] = *(uint2*)pair;
}

// ---------------- gather64_f: 2 nodes per warp; fp32 out (final layer) ----
__global__ void k_gather64_f() {
    int t = blockIdx.x * blockDim.x + threadIdx.x;
    int lane = threadIdx.x & 31;
    int n = ((t >> 5) << 1) + (lane >> 4);
    int l16 = lane & 15;
    if (n >= N_NODES) return;
    const uint2* __restrict__ xw4 = (const uint2*)g_xwh;
    int o0 = g_off[n], o1 = g_off[n + 1];
    float4 acc = h4_to_f4(xw4[(long)n * 16 + l16]);
    int i = o0;
    for (; i + 4 <= o1; i += 4) {
        int r0 = g_csri[i], r1 = g_csri[i + 1], r2 = g_csri[i + 2], r3 = g_csri[i + 3];
        float4 v0 = h4_to_f4(xw4[(long)r0 * 16 + l16]);
        float4 v1 = h4_to_f4(xw4[(long)r1 * 16 + l16]);
        float4 v2 = h4_to_f4(xw4[(long)r2 * 16 + l16]);
        float4 v3 = h4_to_f4(xw4[(long)r3 * 16 + l16]);
        acc.x += (v0.x + v1.x) + (v2.x + v3.x);
        acc.y += (v0.y + v1.y) + (v2.y + v3.y);
        acc.z += (v0.z + v1.z) + (v2.z + v3.z);
        acc.w += (v0.w + v1.w) + (v2.w + v3.w);
    }
    for (; i < o1; i++) {
        float4 v0 = h4_to_f4(xw4[(long)g_csri[i] * 16 + l16]);
        acc.x += v0.x; acc.y += v0.y; acc.z += v0.z; acc.w += v0.w;
    }
    float dv = g_dinv[n];
    acc.x *= dv; acc.y *= dv; acc.z *= dv; acc.w *= dv;
    ((float4*)g_agg)[(long)n * 16 + l16] = acc;
}

// ---------------- GEMM K=64 tensor cores: g_xwh = dinv * (g_aggh @ W) -----
__global__ __launch_bounds__(256) void k_gemmT(const float* __restrict__ W) {
    __shared__ __align__(16) __half Sh[64 * 72];  // A fp16
    __shared__ __align__(16) __half Wh[64 * 72];  // W fp16
    __shared__ float Dv[64];
    const int tid  = threadIdx.x;
    const int base = blockIdx.x * 64;

    if (tid < 64) {
        int row = base + tid;
        Dv[tid] = (row < N_NODES) ? g_dinv[row] : 0.0f;
    }
    // stage A: copy fp16 rows
    for (int i = tid; i < 1024; i += 256) {
        int r = i >> 4, k4 = i & 15;
        int row = base + r;
        uint2 v = make_uint2(0u, 0u);
        if (row < N_NODES) v = *(const uint2*)&g_aggh[(long)row * 64 + k4 * 4];
        *(uint2*)&Sh[r * 72 + k4 * 4] = v;
    }
    // stage W -> fp16
    for (int i = tid; i < 2048; i += 256) {
        int k = i >> 5, j2 = i & 31;
        float2 w = *(const float2*)&W[k * 64 + j2 * 2];
        ((__half2*)Wh)[k * 36 + j2] = __floats2half2_rn(w.x, w.y);
    }
    __syncthreads();

    const int warp = tid >> 5, lane = tid & 31;
    const int m_base = (warp >> 1) * 16;
    const int n_base = (warp & 1) * 32;
    const int lt   = lane & 7;
    const int tile = lane >> 3;

    float d[4][4];
#pragma unroll
    for (int nt = 0; nt < 4; nt++)
#pragma unroll
        for (int q = 0; q < 4; q++) d[nt][q] = 0.f;

#pragma unroll
    for (int kc = 0; kc < 4; kc++) {
        int arow = m_base + lt + ((tile & 1) ? 8 : 0);
        int acol = kc * 16 + ((tile & 2) ? 8 : 0);
        uint32_t a0, a1, a2, a3;
        {
            uint32_t addr = smem_u32(&Sh[arow * 72 + acol]);
            asm volatile("ldmatrix.sync.aligned.m8n8.x4.shared.b16 {%0,%1,%2,%3}, [%4];"
                         : "=r"(a0), "=r"(a1), "=r"(a2), "=r"(a3) : "r"(addr));
        }
#pragma unroll
        for (int g = 0; g < 2; g++) {
            int krow = kc * 16 + lt + ((tile & 1) ? 8 : 0);
            int bcol = n_base + g * 16 + ((tile & 2) ? 8 : 0);
            uint32_t b0, b1, b2, b3;
            uint32_t addr = smem_u32(&Wh[krow * 72 + bcol]);
            asm volatile("ldmatrix.sync.aligned.m8n8.x4.trans.shared.b16 {%0,%1,%2,%3}, [%4];"
                         : "=r"(b0), "=r"(b1), "=r"(b2), "=r"(b3) : "r"(addr));
            asm volatile("mma.sync.aligned.m16n8k16.row.col.f32.f16.f16.f32 "
                         "{%0,%1,%2,%3},{%4,%5,%6,%7},{%8,%9},{%0,%1,%2,%3};"
                         : "+f"(d[g*2][0]), "+f"(d[g*2][1]), "+f"(d[g*2][2]), "+f"(d[g*2][3])
                         : "r"(a0), "r"(a1), "r"(a2), "r"(a3), "r"(b0), "r"(b1));
            asm volatile("mma.sync.aligned.m16n8k16.row.col.f32.f16.f16.f32 "
                         "{%0,%1,%2,%3},{%4,%5,%6,%7},{%8,%9},{%0,%1,%2,%3};"
                         : "+f"(d[g*2+1][0]), "+f"(d[g*2+1][1]), "+f"(d[g*2+1][2]), "+f"(d[g*2+1][3])
                         : "r"(a0), "r"(a1), "r"(a2), "r"(a3), "r"(b2), "r"(b3));
        }
    }

    // epilogue: scale by dinv, fp16 store (y rows)
    const int group = lane >> 2, t4 = lane & 3;
    const int r0g = base + m_base + group;
    const int r1g = r0g + 8;
    const float dv0 = Dv[m_base + group];
    const float dv1 = Dv[m_base + group + 8];
#pragma unroll
    for (int nt = 0; nt < 4; nt++) {
        int ncol = n_base + nt * 8 + t4 * 2;
        if (r0g < N_NODES)
            *(__half2*)&g_xwh[(long)r0g * 64 + ncol] =
                __floats2half2_rn(d[nt][0] * dv0, d[nt][1] * dv0);
        if (r1g < N_NODES)
            *(__half2*)&g_xwh[(long)r1g * 64 + ncol] =
                __floats2half2_rn(d[nt][2] * dv1, d[nt][3] * dv1);
    }
}

// ---------------- pooling (sorted batch, run-length flush, 32-node chunks)
__global__ void k_pool(const float* __restrict__ b4, const int* __restrict__ batch) {
    int j = threadIdx.x & 63;
    int y = threadIdx.x >> 6;
    int start = blockIdx.x * 128 + y * 32;
    int end   = min(start + 32, N_NODES);
    if (start >= end) return;

    float bj = b4[j];
    int   curg = batch[start];
    float mx = 0.f, sm = 0.f;
    int   cnt = 0;

    for (int n = start; n < end; n++) {
        int g = batch[n];
        if (g != curg) {
            atomicMax((int*)&g_gmax[curg * 64 + j], __float_as_int(mx));
            atomicAdd(&g_gsum[curg * 64 + j], sm);
            if (j == 0) atomicAdd(&g_gcnt[curg], (float)cnt);
            curg = g; mx = 0.f; sm = 0.f; cnt = 0;
        }
        float v = fmaxf(g_agg[(long)n * 64 + j] + bj, 0.0f);
        mx = fmaxf(mx, v);
        sm += v;
        cnt++;
    }
    atomicMax((int*)&g_gmax[curg * 64 + j], __float_as_int(mx));
    atomicAdd(&g_gsum[curg * 64 + j], sm);
    if (j == 0) atomicAdd(&g_gcnt[curg], (float)cnt);
}

// ---------------- head ----------------------------------------------------
__global__ void k_head(const float* __restrict__ Wo, const float* __restrict__ bo,
                       float* __restrict__ out, int write_hg) {
    int g = blockIdx.x;
    int j = threadIdx.x;  // 0..127
    float cnt = fmaxf(g_gcnt[g], 1.0f);
    float val = (j < 64) ? g_gmax[g * 64 + j] : g_gsum[g * 64 + (j - 64)] / cnt;
    if (write_hg) out[N_GRAPHS + (long)g * 128 + j] = val;

    float p = val * Wo[j];
#pragma unroll
    for (int off = 16; off > 0; off >>= 1)
        p += __shfl_down_sync(0xffffffff, p, off);

    __shared__ float red[4];
    if ((j & 31) == 0) red[j >> 5] = p;
    __syncthreads();
    if (j == 0) out[g] = red[0] + red[1] + red[2] + red[3] + bo[0];
}

// ---------------- launch ---------------------------------------------------
extern "C" void kernel_launch(void* const* d_in, const int* in_sizes, int n_in,
                              void* d_out, int out_size) {
    const float* x     = (const float*)d_in[0];
    const int*   ei    = (const int*)  d_in[1];   // [2, E]
    const int*   batch = (const int*)  d_in[2];
    const float* W1 = (const float*)d_in[3];  const float* b1 = (const float*)d_in[4];
    const float* W2 = (const float*)d_in[5];  const float* b2 = (const float*)d_in[6];
    const float* W3 = (const float*)d_in[7];  const float* b3 = (const float*)d_in[8];
    const float* W4 = (const float*)d_in[9];  const float* b4 = (const float*)d_in[10];
    const float* Wo = (const float*)d_in[11]; const float* bo = (const float*)d_in[12];

    const int* rows = ei;            // source
    const int* cols = ei + N_EDGES;  // target

    float* out = (float*)d_out;
    int write_hg = (out_size >= N_GRAPHS + N_GRAPHS * 2 * HDIM) ? 1 : 0;

    const int NB_N  = (N_NODES + 255) / 256;
    const int NB_E4 = (N_EDGES / 4 + 255) / 256;

    // CSR build (g_deg arrives zeroed from previous call / load-time init)
    k_deg_count<<<NB_E4, 256>>>(cols);
    k_scan1    <<<SCAN_NB, SCAN_B>>>(x);
    k_scan3    <<<NB_N, 256>>>();
    k_fill     <<<NB_E4, 256>>>(rows, cols);

    const int L1_BLKS  = (N_NODES + 127) / 128;              // 782
    const int GT_BLKS  = (N_NODES + 63) / 64;                // 1563
    const int G64_BLKS = (N_NODES / 2 * 32 + 255) / 256;     // 6250 (2 nodes/warp)

    // layer 1: fused 8-dim gather + GEMM + bias/relu -> g_aggh (h1, fp16)
    k_l1<<<L1_BLKS, 256>>>(W1, b1);
    // layers 2..4: y = dinv*(h @ W) fp16, gather -> h_{l+1} (or preact4 fp32)
    k_gemmT<<<GT_BLKS, 256>>>(W2);
    k_gather64_h<<<G64_BLKS, 256>>>(b2);           // g_aggh = h2
    k_gemmT<<<GT_BLKS, 256>>>(W3);
    k_gather64_h<<<G64_BLKS, 256>>>(b3);           // g_aggh = h3
    k_gemmT<<<GT_BLKS, 256>>>(W4);
    k_gather64_f<<<G64_BLKS, 256>>>();             // g_agg = preact4 (fp32)

    // pooling + head (relu(+b4) fused in pool)
    k_pool<<<(N_NODES + 127) / 128, 256>>>(b4, batch);
    k_head<<<N_GRAPHS, 128>>>(Wo, bo, out, write_hg);
}

// round 17
// speedup vs baseline: 1.8203x; 1.0365x over previous
#include <cuda_runtime.h>
#include <cuda_fp16.h>
#include <cuda_bf16.h>
#include <cstdint>

#define N_NODES 100000
#define N_EDGES 1000000
#define N_GRAPHS 512
#define HDIM 64
#define SCAN_B 1024
#define SCAN_NB ((N_NODES + SCAN_B - 1) / SCAN_B)   // 98

// ---------------- scratch (device globals; never passed from host) --------
__device__ __align__(16) float  g_dinv[N_NODES];
__device__ __align__(16) int    g_deg [N_NODES];
__device__ __align__(16) int    g_off [N_NODES + 1];
__device__ __align__(16) int    g_cur [N_NODES];
__device__ __align__(16) int    g_bsum[SCAN_NB];
__device__ __align__(16) int    g_csri[N_EDGES];          // src index only
__device__ __align__(16) float  g_xs  [N_NODES * 8];      // dinv[n]*x[n]
__device__ __align__(16) __half g_xwh [N_NODES * HDIM];   // y = dinv*xw (fp16)
__device__ __align__(16) __half g_aggh[N_NODES * HDIM];   // h = relu(preact+b) fp16
__device__ __align__(16) float  g_agg [N_NODES * HDIM];   // fp32 preact4 (for pool)
__device__ __align__(16) float  g_gmax[N_GRAPHS * HDIM];
__device__ __align__(16) float  g_gsum[N_GRAPHS * HDIM];
__device__ float g_gcnt[N_GRAPHS];

__device__ __forceinline__ uint32_t smem_u32(const void* p) {
    return (uint32_t)__cvta_generic_to_shared(p);
}

// accumulate 8 halves (uint4) into 8 floats
__device__ __forceinline__ void h8_acc(float* a, uint4 u) {
    float2 p0 = __half22float2(*(__half2*)&u.x);
    float2 p1 = __half22float2(*(__half2*)&u.y);
    float2 p2 = __half22float2(*(__half2*)&u.z);
    float2 p3 = __half22float2(*(__half2*)&u.w);
    a[0] += p0.x; a[1] += p0.y; a[2] += p1.x; a[3] += p1.y;
    a[4] += p2.x; a[5] += p2.y; a[6] += p3.x; a[7] += p3.y;
}

// ---------------- degree count (4 edges/thread) ---------------------------
__global__ void k_deg_count(const int* __restrict__ col) {
    int q = blockIdx.x * blockDim.x + threadIdx.x;
    if (q >= N_EDGES / 4) return;
    int4 c4 = ((const int4*)col)[q];
    atomicAdd(&g_deg[c4.x], 1);
    atomicAdd(&g_deg[c4.y], 1);
    atomicAdd(&g_deg[c4.z], 1);
    atomicAdd(&g_deg[c4.w], 1);
}

// ---------------- scan stage 1: per-chunk scan + dinv + x-prescale +
// deg self-zero ------------------------------------------------------------
__global__ void k_scan1(const float* __restrict__ x) {   // grid SCAN_NB, block 1024
    __shared__ int sh[SCAN_B];
    int idx = threadIdx.x;
    int n = blockIdx.x * SCAN_B + idx;
    int v = 0;
    float dv = 0.0f;
    if (n < N_NODES) {
        v = g_deg[n];
        g_deg[n] = 0;                          // clean for next call
        dv = rsqrtf((float)(v + 1));           // +1 self-loop
        g_dinv[n] = dv;
    }
    sh[idx] = v;
    __syncthreads();
    // prescale x while the scan's smem latency plays out
    if (n < N_NODES) {
        float4 a = ((const float4*)x)[(long)n * 2];
        float4 b = ((const float4*)x)[(long)n * 2 + 1];
        a.x *= dv; a.y *= dv; a.z *= dv; a.w *= dv;
        b.x *= dv; b.y *= dv; b.z *= dv; b.w *= dv;
        ((float4*)g_xs)[(long)n * 2]     = a;
        ((float4*)g_xs)[(long)n * 2 + 1] = b;
    }
#pragma unroll
    for (int d = 1; d < SCAN_B; d <<= 1) {
        int t = (idx >= d) ? sh[idx - d] : 0;
        __syncthreads();
        sh[idx] += t;
        __syncthreads();
    }
    if (n < N_NODES) g_off[n] = sh[idx] - v;          // exclusive (local)
    if (idx == SCAN_B - 1) g_bsum[blockIdx.x] = sh[idx];
}

// ---------------- scan stage 2: apply chunk prefixes + init g_cur +
// zero pooling buffers -----------------------------------------------------
__global__ void k_scan3() {
    __shared__ int sh[128];
    int t = threadIdx.x;
    int v = 0;
    if (t < 128) {
        v = (t < SCAN_NB) ? g_bsum[t] : 0;
        sh[t] = v;
    }
    __syncthreads();
#pragma unroll
    for (int d = 1; d < 128; d <<= 1) {
        int u = 0;
        if (t < 128 && t >= d) u = sh[t - d];
        __syncthreads();
        if (t < 128) sh[t] += u;
        __syncthreads();
    }
    if (t < 128) sh[t] -= v;   // exclusive chunk prefix
    __syncthreads();

    int n = blockIdx.x * 256 + t;
    if (n < N_NODES) {
        int o = g_off[n] + sh[n >> 10];
        g_off[n] = o;
        g_cur[n] = o;
    }
    if (n == 0) g_off[N_NODES] = N_EDGES;
    if (n < N_GRAPHS * HDIM) { g_gmax[n] = 0.0f; g_gsum[n] = 0.0f; }
    if (n < N_GRAPHS) g_gcnt[n] = 0.0f;
}

// ---------------- CSR fill: index only, 4 edges/thread --------------------
__global__ void k_fill(const int* __restrict__ rows, const int* __restrict__ cols) {
    int q = blockIdx.x * blockDim.x + threadIdx.x;
    if (q >= N_EDGES / 4) return;
    int4 r4 = ((const int4*)rows)[q];
    int4 c4 = ((const int4*)cols)[q];
    int s0 = atomicAdd(&g_cur[c4.x], 1);
    int s1 = atomicAdd(&g_cur[c4.y], 1);
    int s2 = atomicAdd(&g_cur[c4.z], 1);
    int s3 = atomicAdd(&g_cur[c4.w], 1);
    g_csri[s0] = r4.x;
    g_csri[s1] = r4.y;
    g_csri[s2] = r4.z;
    g_csri[s3] = r4.w;
}

// ---------------- layer 1 fused: g_aggh = relu((A_hat@x)@W1 + b1) fp16 ----
__global__ void k_l1(const float* __restrict__ W1, const float* __restrict__ b1) {
    __shared__ __align__(16) float W1s[8 * 64];
    __shared__ __align__(16) float A[128 * 8];
    const int tid  = threadIdx.x;
    const int nloc = tid >> 1;
    const int half = tid & 1;
    const int n    = blockIdx.x * 128 + nloc;

    for (int i = tid; i < 512; i += 256) W1s[i] = W1[i];

    if (n < N_NODES) {
        const float4* xs4 = (const float4*)g_xs;
        int o0 = g_off[n], o1 = g_off[n + 1];
        float4 acc = xs4[(long)n * 2 + half];   // own scaled row
        int i = o0;
        for (; i + 4 <= o1; i += 4) {
            int r0 = g_csri[i], r1 = g_csri[i + 1];
            int r2 = g_csri[i + 2], r3 = g_csri[i + 3];
            float4 v0 = xs4[(long)r0 * 2 + half];
            float4 v1 = xs4[(long)r1 * 2 + half];
            float4 v2 = xs4[(long)r2 * 2 + half];
            float4 v3 = xs4[(long)r3 * 2 + half];
            acc.x += (v0.x + v1.x) + (v2.x + v3.x);
            acc.y += (v0.y + v1.y) + (v2.y + v3.y);
            acc.z += (v0.z + v1.z) + (v2.z + v3.z);
            acc.w += (v0.w + v1.w) + (v2.w + v3.w);
        }
        for (; i < o1; i++) {
            float4 v0 = xs4[(long)g_csri[i] * 2 + half];
            acc.x += v0.x; acc.y += v0.y; acc.z += v0.z; acc.w += v0.w;
        }
        float dv = g_dinv[n];
        acc.x *= dv; acc.y *= dv; acc.z *= dv; acc.w *= dv;
        *(float4*)&A[nloc * 8 + half * 4] = acc;
    }
    __syncthreads();

    if (n < N_NODES) {
        float a[8];
        *(float4*)&a[0] = *(const float4*)&A[nloc * 8];
        *(float4*)&a[4] = *(const float4*)&A[nloc * 8 + 4];
        const int jc0 = half * 32;
        float4 acc[8];
#pragma unroll
        for (int g = 0; g < 8; g++) acc[g] = make_float4(0.f, 0.f, 0.f, 0.f);
#pragma unroll
        for (int k = 0; k < 8; k++) {
            float ak = a[k];
#pragma unroll
            for (int g = 0; g < 8; g++) {
                float4 w = *(const float4*)&W1s[k * 64 + jc0 + g * 4];
                acc[g].x = fmaf(ak, w.x, acc[g].x);
                acc[g].y = fmaf(ak, w.y, acc[g].y);
                acc[g].z = fmaf(ak, w.z, acc[g].z);
                acc[g].w = fmaf(ak, w.w, acc[g].w);
            }
        }
        // epilogue: h1 = relu(preact1 + b1) -> fp16
#pragma unroll
        for (int g = 0; g < 8; g++) {
            int j = jc0 + g * 4;
            float4 bb = *(const float4*)&b1[j];
            __half2 p0 = __floats2half2_rn(fmaxf(acc[g].x + bb.x, 0.f),
                                           fmaxf(acc[g].y + bb.y, 0.f));
            __half2 p1 = __floats2half2_rn(fmaxf(acc[g].z + bb.z, 0.f),
                                           fmaxf(acc[g].w + bb.w, 0.f));
            __half2 pair[2] = {p0, p1};
            *(uint2*)&g_aggh[(long)n * 64 + j] = *(uint2*)pair;
        }
    }
}

// ---------------- gather64_h: 4 nodes per warp, 8 lanes/node, uint4 lanes.
// g_aggh = relu(dinv*(y[c]+sum y[r]) + b) fp16
__global__ void k_gather64_h(const float* __restrict__ bias) {
    int t = blockIdx.x * blockDim.x + threadIdx.x;
    int lane = threadIdx.x & 31;
    int n = ((t >> 5) << 2) + (lane >> 3);    // 4 nodes per warp
    int l8 = lane & 7;                        // 16B slice within node
    if (n >= N_NODES) return;
    const uint4* __restrict__ xw8 = (const uint4*)g_xwh;  // 8 halves per entry
    int o0 = g_off[n], o1 = g_off[n + 1];
    float a[8] = {0.f, 0.f, 0.f, 0.f, 0.f, 0.f, 0.f, 0.f};
    h8_acc(a, xw8[(long)n * 8 + l8]);                     // own y row
    int i = o0;
    for (; i + 4 <= o1; i += 4) {
        int r0 = g_csri[i], r1 = g_csri[i + 1], r2 = g_csri[i + 2], r3 = g_csri[i + 3];
        uint4 u0 = xw8[(long)r0 * 8 + l8];
        uint4 u1 = xw8[(long)r1 * 8 + l8];
        uint4 u2 = xw8[(long)r2 * 8 + l8];
        uint4 u3 = xw8[(long)r3 * 8 + l8];
        h8_acc(a, u0); h8_acc(a, u1); h8_acc(a, u2); h8_acc(a, u3);
    }
    for (; i < o1; i++)
        h8_acc(a, xw8[(long)g_csri[i] * 8 + l8]);
    float dv = g_dinv[n];
    const float* bb = &bias[l8 * 8];
    __half2 p[4];
#pragma unroll
    for (int q = 0; q < 4; q++)
        p[q] = __floats2half2_rn(fmaxf(a[q * 2] * dv + bb[q * 2], 0.f),
                                 fmaxf(a[q * 2 + 1] * dv + bb[q * 2 + 1], 0.f));
    ((uint4*)g_aggh)[(long)n * 8 + l8] = *(uint4*)p;
}

// ---------------- gather64_f: 4 nodes per warp; fp32 out (final layer) ----
__global__ void k_gather64_f() {
    int t = blockIdx.x * blockDim.x + threadIdx.x;
    int lane = threadIdx.x & 31;
    int n = ((t >> 5) << 2) + (lane >> 3);
    int l8 = lane & 7;
    if (n >= N_NODES) return;
    const uint4* __restrict__ xw8 = (const uint4*)g_xwh;
    int o0 = g_off[n], o1 = g_off[n + 1];
    float a[8] = {0.f, 0.f, 0.f, 0.f, 0.f, 0.f, 0.f, 0.f};
    h8_acc(a, xw8[(long)n * 8 + l8]);
    int i = o0;
    for (; i + 4 <= o1; i += 4) {
        int r0 = g_csri[i], r1 = g_csri[i + 1], r2 = g_csri[i + 2], r3 = g_csri[i + 3];
        uint4 u0 = xw8[(long)r0 * 8 + l8];
        uint4 u1 = xw8[(long)r1 * 8 + l8];
        uint4 u2 = xw8[(long)r2 * 8 + l8];
        uint4 u3 = xw8[(long)r3 * 8 + l8];
        h8_acc(a, u0); h8_acc(a, u1); h8_acc(a, u2); h8_acc(a, u3);
    }
    for (; i < o1; i++)
        h8_acc(a, xw8[(long)g_csri[i] * 8 + l8]);
    float dv = g_dinv[n];
#pragma unroll
    for (int q = 0; q < 8; q++) a[q] *= dv;
    ((float4*)g_agg)[(long)n * 16 + l8 * 2]     = *(float4*)&a[0];
    ((float4*)g_agg)[(long)n * 16 + l8 * 2 + 1] = *(float4*)&a[4];
}

// ---------------- GEMM K=64 tensor cores: g_xwh = dinv * (g_aggh @ W) -----
__global__ __launch_bounds__(256) void k_gemmT(const float* __restrict__ W) {
    __shared__ __align__(16) __half Sh[64 * 72];  // A fp16
    __shared__ __align__(16) __half Wh[64 * 72];  // W fp16
    __shared__ float Dv[64];
    const int tid  = threadIdx.x;
    const int base = blockIdx.x * 64;

    if (tid < 64) {
        int row = base + tid;
        Dv[tid] = (row < N_NODES) ? g_dinv[row] : 0.0f;
    }
    // stage A: copy fp16 rows
    for (int i = tid; i < 1024; i += 256) {
        int r = i >> 4, k4 = i & 15;
        int row = base + r;
        uint2 v = make_uint2(0u, 0u);
        if (row < N_NODES) v = *(const uint2*)&g_aggh[(long)row * 64 + k4 * 4];
        *(uint2*)&Sh[r * 72 + k4 * 4] = v;
    }
    // stage W -> fp16
    for (int i = tid; i < 2048; i += 256) {
        int k = i >> 5, j2 = i & 31;
        float2 w = *(const float2*)&W[k * 64 + j2 * 2];
        ((__half2*)Wh)[k * 36 + j2] = __floats2half2_rn(w.x, w.y);
    }
    __syncthreads();

    const int warp = tid >> 5, lane = tid & 31;
    const int m_base = (warp >> 1) * 16;
    const int n_base = (warp & 1) * 32;
    const int lt   = lane & 7;
    const int tile = lane >> 3;

    float d[4][4];
#pragma unroll
    for (int nt = 0; nt < 4; nt++)
#pragma unroll
        for (int q = 0; q < 4; q++) d[nt][q] = 0.f;

#pragma unroll
    for (int kc = 0; kc < 4; kc++) {
        int arow = m_base + lt + ((tile & 1) ? 8 : 0);
        int acol = kc * 16 + ((tile & 2) ? 8 : 0);
        uint32_t a0, a1, a2, a3;
        {
            uint32_t addr = smem_u32(&Sh[arow * 72 + acol]);
            asm volatile("ldmatrix.sync.aligned.m8n8.x4.shared.b16 {%0,%1,%2,%3}, [%4];"
                         : "=r"(a0), "=r"(a1), "=r"(a2), "=r"(a3) : "r"(addr));
        }
#pragma unroll
        for (int g = 0; g < 2; g++) {
            int krow = kc * 16 + lt + ((tile & 1) ? 8 : 0);
            int bcol = n_base + g * 16 + ((tile & 2) ? 8 : 0);
            uint32_t b0, b1, b2, b3;
            uint32_t addr = smem_u32(&Wh[krow * 72 + bcol]);
            asm volatile("ldmatrix.sync.aligned.m8n8.x4.trans.shared.b16 {%0,%1,%2,%3}, [%4];"
                         : "=r"(b0), "=r"(b1), "=r"(b2), "=r"(b3) : "r"(addr));
            asm volatile("mma.sync.aligned.m16n8k16.row.col.f32.f16.f16.f32 "
                         "{%0,%1,%2,%3},{%4,%5,%6,%7},{%8,%9},{%0,%1,%2,%3};"
                         : "+f"(d[g*2][0]), "+f"(d[g*2][1]), "+f"(d[g*2][2]), "+f"(d[g*2][3])
                         : "r"(a0), "r"(a1), "r"(a2), "r"(a3), "r"(b0), "r"(b1));
            asm volatile("mma.sync.aligned.m16n8k16.row.col.f32.f16.f16.f32 "
                         "{%0,%1,%2,%3},{%4,%5,%6,%7},{%8,%9},{%0,%1,%2,%3};"
                         : "+f"(d[g*2+1][0]), "+f"(d[g*2+1][1]), "+f"(d[g*2+1][2]), "+f"(d[g*2+1][3])
                         : "r"(a0), "r"(a1), "r"(a2), "r"(a3), "r"(b2), "r"(b3));
        }
    }

    // epilogue: scale by dinv, fp16 store (y rows)
    const int group = lane >> 2, t4 = lane & 3;
    const int r0g = base + m_base + group;
    const int r1g = r0g + 8;
    const float dv0 = Dv[m_base + group];
    const float dv1 = Dv[m_base + group + 8];
#pragma unroll
    for (int nt = 0; nt < 4; nt++) {
        int ncol = n_base + nt * 8 + t4 * 2;
        if (r0g < N_NODES)
            *(__half2*)&g_xwh[(long)r0g * 64 + ncol] =
                __floats2half2_rn(d[nt][0] * dv0, d[nt][1] * dv0);
        if (r1g < N_NODES)
            *(__half2*)&g_xwh[(long)r1g * 64 + ncol] =
                __floats2half2_rn(d[nt][2] * dv1, d[nt][3] * dv1);
    }
}

// ---------------- pooling (sorted batch, run-length flush, 32-node chunks)
__global__ void k_pool(const float* __restrict__ b4, const int* __restrict__ batch) {
    int j = threadIdx.x & 63;
    int y = threadIdx.x >> 6;
    int start = blockIdx.x * 128 + y * 32;
    int end   = min(start + 32, N_NODES);
    if (start >= end) return;

    float bj = b4[j];
    int   curg = batch[start];
    float mx = 0.f, sm = 0.f;
    int   cnt = 0;

    for (int n = start; n < end; n++) {
        int g = batch[n];
        if (g != curg) {
            atomicMax((int*)&g_gmax[curg * 64 + j], __float_as_int(mx));
            atomicAdd(&g_gsum[curg * 64 + j], sm);
            if (j == 0) atomicAdd(&g_gcnt[curg], (float)cnt);
            curg = g; mx = 0.f; sm = 0.f; cnt = 0;
        }
        float v = fmaxf(g_agg[(long)n * 64 + j] + bj, 0.0f);
        mx = fmaxf(mx, v);
        sm += v;
        cnt++;
    }
    atomicMax((int*)&g_gmax[curg * 64 + j], __float_as_int(mx));
    atomicAdd(&g_gsum[curg * 64 + j], sm);
    if (j == 0) atomicAdd(&g_gcnt[curg], (float)cnt);
}

// ---------------- head ----------------------------------------------------
__global__ void k_head(const float* __restrict__ Wo, const float* __restrict__ bo,
                       float* __restrict__ out, int write_hg) {
    int g = blockIdx.x;
    int j = threadIdx.x;  // 0..127
    float cnt = fmaxf(g_gcnt[g], 1.0f);
    float val = (j < 64) ? g_gmax[g * 64 + j] : g_gsum[g * 64 + (j - 64)] / cnt;
    if (write_hg) out[N_GRAPHS + (long)g * 128 + j] = val;

    float p = val * Wo[j];
#pragma unroll
    for (int off = 16; off > 0; off >>= 1)
        p += __shfl_down_sync(0xffffffff, p, off);

    __shared__ float red[4];
    if ((j & 31) == 0) red[j >> 5] = p;
    __syncthreads();
    if (j == 0) out[g] = red[0] + red[1] + red[2] + red[3] + bo[0];
}

// ---------------- launch ---------------------------------------------------
extern "C" void kernel_launch(void* const* d_in, const int* in_sizes, int n_in,
                              void* d_out, int out_size) {
    const float* x     = (const float*)d_in[0];
    const int*   ei    = (const int*)  d_in[1];   // [2, E]
    const int*   batch = (const int*)  d_in[2];
    const float* W1 = (const float*)d_in[3];  const float* b1 = (const float*)d_in[4];
    const float* W2 = (const float*)d_in[5];  const float* b2 = (const float*)d_in[6];
    const float* W3 = (const float*)d_in[7];  const float* b3 = (const float*)d_in[8];
    const float* W4 = (const float*)d_in[9];  const float* b4 = (const float*)d_in[10];
    const float* Wo = (const float*)d_in[11]; const float* bo = (const float*)d_in[12];

    const int* rows = ei;            // source
    const int* cols = ei + N_EDGES;  // target

    float* out = (float*)d_out;
    int write_hg = (out_size >= N_GRAPHS + N_GRAPHS * 2 * HDIM) ? 1 : 0;

    const int NB_N  = (N_NODES + 255) / 256;
    const int NB_E4 = (N_EDGES / 4 + 255) / 256;

    // CSR build (g_deg arrives zeroed from previous call / load-time init)
    k_deg_count<<<NB_E4, 256>>>(cols);
    k_scan1    <<<SCAN_NB, SCAN_B>>>(x);
    k_scan3    <<<NB_N, 256>>>();
    k_fill     <<<NB_E4, 256>>>(rows, cols);

    const int L1_BLKS  = (N_NODES + 127) / 128;              // 782
    const int GT_BLKS  = (N_NODES + 63) / 64;                // 1563
    const int G64_BLKS = (N_NODES / 4 * 32 + 255) / 256;     // 3125 (4 nodes/warp)

    // layer 1: fused 8-dim gather + GEMM + bias/relu -> g_aggh (h1, fp16)
    k_l1<<<L1_BLKS, 256>>>(W1, b1);
    // layers 2..4: y = dinv*(h @ W) fp16, gather -> h_{l+1} (or preact4 fp32)
    k_gemmT<<<GT_BLKS, 256>>>(W2);
    k_gather64_h<<<G64_BLKS, 256>>>(b2);           // g_aggh = h2
    k_gemmT<<<GT_BLKS, 256>>>(W3);
    k_gather64_h<<<G64_BLKS, 256>>>(b3);           // g_aggh = h3
    k_gemmT<<<GT_BLKS, 256>>>(W4);
    k_gather64_f<<<G64_BLKS, 256>>>();             // g_agg = preact4 (fp32)

    // pooling + head (relu(+b4) fused in pool)
    k_pool<<<(N_NODES + 127) / 128, 256>>>(b4, batch);
    k_head<<<N_GRAPHS, 128>>>(Wo, bo, out, write_hg);
}